// round 8
// baseline (speedup 1.0000x reference)
#include <cuda_runtime.h>
#include <math.h>

#define NB   2
#define NPTS 8192
#define KNN  20
#define GDIM 32
#define G3   (GDIM*GDIM*GDIM)
#define QPBQ 64     // queries per query-block
#define QSPL 4      // splits per query

// ---------------- device scratch (no allocation allowed) ----------------
__device__ int    g_knn[NB * NPTS * KNN];
__device__ float  g_S1[128], g_S2[128], g_SN[64];
__device__ float  g_base1[NB][128];
__device__ float  g_baseN[NB][64];
// grid structures
__device__ float4 g_pts4[NB * NPTS];          // cell-sorted (x,y,z, bits(orig id))
__device__ int    g_cellstart[NB * (G3 + 1)]; // CSR starts per batch
__device__ int    g_cnt[NB * G3];             // counts, then scatter cursors
__device__ float  g_lo[NB][3];
__device__ float  g_invs[NB][3];
__device__ float  g_smin[NB];

// exact-ish gelu (tanh via exp) for the tiny setup MLP
__device__ __forceinline__ float gelu_f(float x) {
    float y = 0.7978845608028654f * (x + 0.044715f * x * x * x);
    float e = __expf(2.0f * y);
    float th = 1.0f - 2.0f / (e + 1.0f);
    return 0.5f * x * (1.0f + th);
}

// fast gelu: tanh.approx.f32
__device__ __forceinline__ float gelu_fast(float x) {
    float y = 0.7978845608028654f * fmaf(0.044715f * x * x, x, x);
    float t;
    asm("tanh.approx.f32 %0, %1;" : "=f"(t) : "f"(y));
    return 0.5f * x * (1.0f + t);
}

__device__ __forceinline__ int cell_of(float v, float lo, float inv) {
    int i = (int)((v - lo) * inv);
    return i < 0 ? 0 : (i > GDIM - 1 ? GDIM - 1 : i);
}

// ---------------- grid kernel 1: zero counts + bbox (one block per batch) ----------------
__global__ __launch_bounds__(256) void grid_bbox_kernel(const float* __restrict__ z)
{
    const int b   = blockIdx.x;
    const int tid = threadIdx.x;
    const unsigned FULL = 0xffffffffu;

    for (int i = tid; i < G3; i += 256) g_cnt[b * G3 + i] = 0;

    float lx = 1e30f, ly = 1e30f, lz = 1e30f;
    float hx = -1e30f, hy = -1e30f, hz = -1e30f;
    const float* zb = z + (size_t)b * NPTS * 7;
    for (int n = tid; n < NPTS; n += 256) {
        const float* p = zb + (size_t)n * 7;
        float x = p[0], y = p[1], w = p[2];
        lx = fminf(lx, x); hx = fmaxf(hx, x);
        ly = fminf(ly, y); hy = fmaxf(hy, y);
        lz = fminf(lz, w); hz = fmaxf(hz, w);
    }
#pragma unroll
    for (int off = 16; off > 0; off >>= 1) {
        lx = fminf(lx, __shfl_xor_sync(FULL, lx, off));
        ly = fminf(ly, __shfl_xor_sync(FULL, ly, off));
        lz = fminf(lz, __shfl_xor_sync(FULL, lz, off));
        hx = fmaxf(hx, __shfl_xor_sync(FULL, hx, off));
        hy = fmaxf(hy, __shfl_xor_sync(FULL, hy, off));
        hz = fmaxf(hz, __shfl_xor_sync(FULL, hz, off));
    }
    __shared__ float slo[8][3], shi[8][3];
    const int warp = tid >> 5;
    if ((tid & 31) == 0) {
        slo[warp][0] = lx; slo[warp][1] = ly; slo[warp][2] = lz;
        shi[warp][0] = hx; shi[warp][1] = hy; shi[warp][2] = hz;
    }
    __syncthreads();
    if (tid == 0) {
        for (int w2 = 1; w2 < 8; w2++) {
            slo[0][0] = fminf(slo[0][0], slo[w2][0]);
            slo[0][1] = fminf(slo[0][1], slo[w2][1]);
            slo[0][2] = fminf(slo[0][2], slo[w2][2]);
            shi[0][0] = fmaxf(shi[0][0], shi[w2][0]);
            shi[0][1] = fmaxf(shi[0][1], shi[w2][1]);
            shi[0][2] = fmaxf(shi[0][2], shi[w2][2]);
        }
        float smin = 1e30f;
        for (int d = 0; d < 3; d++) {
            float span = fmaxf(shi[0][d] - slo[0][d], 1e-5f);
            g_lo[b][d]   = slo[0][d];
            g_invs[b][d] = (float)GDIM / span;
            smin = fminf(smin, span / (float)GDIM);
        }
        g_smin[b] = smin;
    }
}

// ---------------- grid kernel 2: count points per cell ----------------
__global__ __launch_bounds__(256) void grid_count_kernel(const float* __restrict__ z)
{
    int i = blockIdx.x * 256 + threadIdx.x;
    int b = i >> 13;
    int n = i & (NPTS - 1);
    const float* p = z + ((size_t)b * NPTS + n) * 7;
    int cx = cell_of(p[0], g_lo[b][0], g_invs[b][0]);
    int cy = cell_of(p[1], g_lo[b][1], g_invs[b][1]);
    int cz = cell_of(p[2], g_lo[b][2], g_invs[b][2]);
    int c = (cx * GDIM + cy) * GDIM + cz;
    atomicAdd(&g_cnt[b * G3 + c], 1);
}

// ---------------- grid kernel 3: exclusive scan (one 1024-thr block per batch) ----------------
__global__ __launch_bounds__(1024) void grid_scan_kernel()
{
    __shared__ int sm[1024];
    const int b = blockIdx.x;
    const int t = threadIdx.x;
    const int base = t * 32;

    int sum = 0;
    for (int k = 0; k < 32; k++) sum += g_cnt[b * G3 + base + k];
    sm[t] = sum;
    __syncthreads();
    for (int off = 1; off < 1024; off <<= 1) {
        int v = (t >= off) ? sm[t - off] : 0;
        __syncthreads();
        sm[t] += v;
        __syncthreads();
    }
    int running = sm[t] - sum;   // exclusive prefix
    for (int k = 0; k < 32; k++) {
        int c = base + k;
        int cc = g_cnt[b * G3 + c];
        g_cellstart[b * (G3 + 1) + c] = running;
        g_cnt[b * G3 + c] = running;   // becomes scatter cursor
        running += cc;
    }
    if (t == 1023) g_cellstart[b * (G3 + 1) + G3] = running;  // == NPTS
}

// ---------------- grid kernel 4: scatter points into cell-sorted order ----------------
__global__ __launch_bounds__(256) void grid_scatter_kernel(const float* __restrict__ z)
{
    int i = blockIdx.x * 256 + threadIdx.x;
    int b = i >> 13;
    int n = i & (NPTS - 1);
    const float* p = z + ((size_t)b * NPTS + n) * 7;
    float x = p[0], y = p[1], w = p[2];
    int cx = cell_of(x, g_lo[b][0], g_invs[b][0]);
    int cy = cell_of(y, g_lo[b][1], g_invs[b][1]);
    int cz = cell_of(w, g_lo[b][2], g_invs[b][2]);
    int c = (cx * GDIM + cy) * GDIM + cz;
    int pos = atomicAdd(&g_cnt[b * G3 + c], 1);
    g_pts4[b * NPTS + pos] = make_float4(x, y, w, __int_as_float(n));
}

// ---------------- grid kernel 5: exact kNN via expanding rings, 4 splits/query ----------------
// 256 threads = 64 queries x 4 splits; a query's splits are 4 adjacent lanes
// of one warp. Ring cells are dealt round-robin by visit counter; each split
// keeps its own top-20. Stop rule: union-20th <= min over splits of bd[19],
// so ub <= (rho*smin)^2 is a safe stop. Warp stays converged via done-flag.
__global__ __launch_bounds__(256) void knn_query_kernel()
{
    __shared__ float2 mg[QPBQ][KNN * QSPL];   // 40 KB

    const unsigned FULL = 0xffffffffu;
    const int tid  = threadIdx.x;
    const int b    = blockIdx.y;
    const int lqq  = tid >> 2;                // local query 0..63
    const int s    = tid & 3;                 // split
    const int slot = blockIdx.x * QPBQ + lqq;

    const float4* pts = g_pts4 + (size_t)b * NPTS;
    const int* cs = g_cellstart + (size_t)b * (G3 + 1);

    float4 q4 = pts[slot];
    const float qx = q4.x, qy = q4.y, qz = q4.z;
    const int n = __float_as_int(q4.w);

    const int cx = cell_of(qx, g_lo[b][0], g_invs[b][0]);
    const int cy = cell_of(qy, g_lo[b][1], g_invs[b][1]);
    const int cz = cell_of(qz, g_lo[b][2], g_invs[b][2]);
    const float smin = g_smin[b];

    float bd[KNN];
    int   bi[KNN];
#pragma unroll
    for (int k = 0; k < KNN; k++) { bd[k] = 1e30f; bi[k] = -1; }

    bool done = false;
    for (int rho = 0; rho <= 2 * GDIM; rho++) {
        if (!done) {
            int x0 = max(cx - rho, 0), x1 = min(cx + rho, GDIM - 1);
            int y0 = max(cy - rho, 0), y1 = min(cy + rho, GDIM - 1);
            int z0 = max(cz - rho, 0), z1 = min(cz + rho, GDIM - 1);
            int ccnt = 0;

            for (int ix = x0; ix <= x1; ix++) {
                bool bx = (ix == cx - rho) || (ix == cx + rho);
                for (int iy = y0; iy <= y1; iy++) {
                    bool bxy = bx || (iy == cy - rho) || (iy == cy + rho);
                    int zs, ze, zstep;
                    if (bxy) { zs = z0; ze = z1; zstep = 1; }
                    else     { zs = cz - rho; ze = cz + rho; zstep = (2 * rho > 0 ? 2 * rho : 1); }
                    for (int iz = zs; iz <= ze; iz += zstep) {
                        if (iz < 0 || iz > GDIM - 1) continue;
                        if ((ccnt++ & 3) != s) continue;      // my quarter of cells
                        int c = (ix * GDIM + iy) * GDIM + iz;
                        int st = cs[c], en = cs[c + 1];
                        for (int j = st; j < en; j++) {
                            float4 t4 = pts[j];
                            float dx = qx - t4.x;
                            float dy = qy - t4.y;
                            float dz = qz - t4.z;
                            float d2 = fmaf(dx, dx, fmaf(dy, dy, dz * dz));
                            if (d2 < bd[KNN - 1]) {
                                int id = __float_as_int(t4.w);
                                if (id != n) {
#pragma unroll
                                    for (int k = KNN - 1; k > 0; --k) {
                                        if (bd[k] > d2) {
                                            bool sh = bd[k - 1] > d2;
                                            bd[k] = sh ? bd[k - 1] : d2;
                                            bi[k] = sh ? bi[k - 1] : id;
                                        }
                                    }
                                    if (bd[0] > d2) { bd[0] = d2; bi[0] = id; }
                                }
                            }
                        }
                    }
                }
            }
        }
        // union-20th upper bound across the 4 splits of this query
        float ub = bd[KNN - 1];
        ub = fminf(ub, __shfl_xor_sync(FULL, ub, 1));
        ub = fminf(ub, __shfl_xor_sync(FULL, ub, 2));
        float bound = (float)rho * smin;
        if (ub <= bound * bound * 0.998f) done = true;
        if (rho >= 2 * GDIM - 1) done = true;
        if (__all_sync(FULL, done)) break;
    }

    // 4-way merge per query
#pragma unroll
    for (int k = 0; k < KNN; k++)
        mg[lqq][s * KNN + k] = make_float2(bd[k], __int_as_float(bi[k]));
    __syncwarp(FULL);

    if (s == 0) {
        float fd[KNN]; int fi[KNN];
#pragma unroll
        for (int k = 0; k < KNN; k++) { fd[k] = 1e30f; fi[k] = -1; }
        for (int i = 0; i < KNN * QSPL; i++) {
            float2 c = mg[lqq][i];
            float d = c.x;
            if (d < fd[KNN - 1]) {
                int id = __float_as_int(c.y);
#pragma unroll
                for (int k = KNN - 1; k > 0; --k) {
                    if (fd[k] > d) {
                        bool sh = fd[k - 1] > d;
                        fd[k] = sh ? fd[k - 1] : d;
                        fi[k] = sh ? fi[k - 1] : id;
                    }
                }
                if (fd[0] > d) { fd[0] = d; fi[0] = id; }
            }
        }
        int* o = g_knn + ((size_t)b * NPTS + n) * KNN;
#pragma unroll
        for (int k = 0; k < KNN; k++) o[k] = fi[k];
    }
}

// ---------------- kernel: cond MLP + folded per-batch vectors ----------------
__global__ __launch_bounds__(256) void setup_kernel(
    const float* __restrict__ t, const float* __restrict__ conditioning,
    const float* __restrict__ Wc1, const float* __restrict__ bc1,
    const float* __restrict__ Wc2, const float* __restrict__ bc2,
    const float* __restrict__ Wc3, const float* __restrict__ bc3,
    const float* __restrict__ We1, const float* __restrict__ be1,
    const float* __restrict__ Wn1, const float* __restrict__ bn1)
{
    const unsigned FULL = 0xffffffffu;
    const int tid  = threadIdx.x;
    const int lane = tid & 31;
    const int warp = tid >> 5;

    if (tid < 128) {
        float s1 = 0.f, s2 = 0.f;
#pragma unroll
        for (int c = 0; c < 36; c++) {
            s1 += We1[c * 128 + tid];
            s2 += We1[(36 + c) * 128 + tid];
        }
        g_S1[tid] = s1;
        g_S2[tid] = s2;
    }
    if (tid < 64) {
        float sn = 0.f;
#pragma unroll
        for (int c = 0; c < 36; c++) sn += Wn1[c * 64 + tid];
        g_SN[tid] = sn;
    }

    __shared__ float sc[36], h1[144], h2[144], cv[40];

    for (int b = 0; b < NB; b++) {
        if (tid < 36) {
            float v;
            if (tid < 16) {
                float f = expf(-logf(10000.0f) * (float)tid / 15.0f);
                v = sinf(t[b] * f);
            } else if (tid < 32) {
                int i = tid - 16;
                float f = expf(-logf(10000.0f) * (float)i / 15.0f);
                v = cosf(t[b] * f);
            } else {
                v = conditioning[b * 4 + (tid - 32)];
            }
            sc[tid] = v;
        }
        __syncthreads();
        if (tid < 144) {
            float a = bc1[tid];
#pragma unroll
            for (int c = 0; c < 36; c++) a = fmaf(sc[c], Wc1[c * 144 + tid], a);
            h1[tid] = gelu_f(a);
        }
        __syncthreads();
        for (int o = 0; o < 18; o++) {
            int j = warp + 8 * o;
            float a = 0.f;
#pragma unroll
            for (int r = 0; r < 5; r++) {
                int c = lane + 32 * r;
                if (c < 144) a = fmaf(h1[c], Wc2[c * 144 + j], a);
            }
#pragma unroll
            for (int off = 16; off > 0; off >>= 1)
                a += __shfl_xor_sync(FULL, a, off);
            if (lane == 0) h2[j] = gelu_f(a + bc2[j]);
        }
        __syncthreads();
        for (int o = 0; o < 5; o++) {
            int j = warp + 8 * o;
            if (j < 36) {
                float a = 0.f;
#pragma unroll
                for (int r = 0; r < 5; r++) {
                    int c = lane + 32 * r;
                    if (c < 144) a = fmaf(h2[c], Wc3[c * 36 + j], a);
                }
#pragma unroll
                for (int off = 16; off > 0; off >>= 1)
                    a += __shfl_xor_sync(FULL, a, off);
                if (lane == 0) cv[j] = a + bc3[j];
            }
        }
        __syncthreads();
        if (tid < 128) {
            float a = be1[tid];
#pragma unroll
            for (int c = 0; c < 36; c++)
                a = fmaf(cv[c], We1[c * 128 + tid] + We1[(36 + c) * 128 + tid], a);
            g_base1[b][tid] = a;
        }
        if (tid < 64) {
            float a = bn1[tid];
#pragma unroll
            for (int c = 0; c < 36; c++) a = fmaf(cv[c], Wn1[c * 64 + tid], a);
            g_baseN[b][tid] = a;
        }
        __syncthreads();
    }
}

// ---------------- kernel: edge MLP + softmax + aggregation + node MLP ----------------
__global__ __launch_bounds__(256) void main_kernel(
    const float* __restrict__ z,
    const float* __restrict__ We1, const float* __restrict__ We2,
    const float* __restrict__ be2,
    const float* __restrict__ Wn1, const float* __restrict__ Wn2,
    const float* __restrict__ bn2,
    const float* __restrict__ alpha, const float* __restrict__ beta,
    float* __restrict__ out)
{
    __shared__ float4 part[8][KNN][17];

    const unsigned FULL = 0xffffffffu;
    const int wlocal = threadIdx.x >> 5;
    const int warp = (blockIdx.x * blockDim.x + threadIdx.x) >> 5;
    const int lane = threadIdx.x & 31;
    const int b = warp >> 13;
    const int n = warp & (NPTS - 1);

    const float* zb = z + (size_t)b * NPTS * 7;
    const float* zt = zb + (size_t)n * 7;
    const float ptx = zt[0], pty = zt[1], ptz = zt[2];
    const float vtx = zt[3], vty = zt[4], vtz = zt[5];
    const float mt  = zt[6];

    float relx = 0.f, rely = 0.f, relz = 0.f;
    float vsx = 0.f, vsy = 0.f, vsz = 0.f;
    float msrc = 0.f, r2 = 0.f, dvv = 0.f, dvr = 0.f, dtr = 0.f;
    if (lane < KNN) {
        int src = g_knn[(size_t)warp * KNN + lane];
        const float* zs = zb + (size_t)src * 7;
        float sx = zs[0], sy = zs[1], sz = zs[2];
        vsx = zs[3]; vsy = zs[4]; vsz = zs[5]; msrc = zs[6];
        relx = sx - ptx; rely = sy - pty; relz = sz - ptz;
        r2  = relx * relx + rely * rely + relz * relz;
        dvv = vsx * vtx + vsy * vty + vsz * vtz;
        dvr = vsx * relx + vsy * rely + vsz * relz;
        dtr = vtx * relx + vty * rely + vtz * relz;
    }

    float s1[4], s2[4], w72[4], w73[4], w74[4], w75[4], b1[4];
    float4 we2[4];
#pragma unroll
    for (int qq = 0; qq < 4; qq++) {
        int j = lane + 32 * qq;
        s1[qq]  = g_S1[j];
        s2[qq]  = g_S2[j];
        w72[qq] = We1[72 * 128 + j];
        w73[qq] = We1[73 * 128 + j];
        w74[qq] = We1[74 * 128 + j];
        w75[qq] = We1[75 * 128 + j];
        b1[qq]  = g_base1[b][j];
        we2[qq] = ((const float4*)We2)[j];
    }

#pragma unroll
    for (int e = 0; e < KNN; e++) {
        float em   = __shfl_sync(FULL, msrc, e);
        float er2  = __shfl_sync(FULL, r2,   e);
        float edvv = __shfl_sync(FULL, dvv,  e);
        float edvr = __shfl_sync(FULL, dvr,  e);
        float edtr = __shfl_sync(FULL, dtr,  e);
        float p0 = 0.f, p1 = 0.f, p2 = 0.f, p3 = 0.f;
#pragma unroll
        for (int qq = 0; qq < 4; qq++) {
            float h = b1[qq];
            h = fmaf(em,   s1[qq],  h);
            h = fmaf(mt,   s2[qq],  h);
            h = fmaf(er2,  w72[qq], h);
            h = fmaf(edvv, w73[qq], h);
            h = fmaf(edvr, w74[qq], h);
            h = fmaf(edtr, w75[qq], h);
            float g = gelu_fast(h);
            p0 = fmaf(g, we2[qq].x, p0);
            p1 = fmaf(g, we2[qq].y, p1);
            p2 = fmaf(g, we2[qq].z, p2);
            p3 = fmaf(g, we2[qq].w, p3);
        }
        p0 += __shfl_xor_sync(FULL, p0, 16);
        p1 += __shfl_xor_sync(FULL, p1, 16);
        p2 += __shfl_xor_sync(FULL, p2, 16);
        p3 += __shfl_xor_sync(FULL, p3, 16);
        if (lane < 16) part[wlocal][e][lane] = make_float4(p0, p1, p2, p3);
    }
    __syncwarp();

    float elog = -1e30f, esmsg = 0.f, ecrel = 0.f, ecvel = 0.f;
    if (lane < KNN) {
        float4 acc = part[wlocal][lane][0];
#pragma unroll
        for (int i = 1; i < 16; i++) {
            float4 p = part[wlocal][lane][i];
            acc.x += p.x; acc.y += p.y; acc.z += p.z; acc.w += p.w;
        }
        elog  = acc.x + be2[0];
        esmsg = acc.y + be2[1];
        ecrel = acc.z + be2[2];
        ecvel = acc.w + be2[3];
    }

    float lg = (lane < KNN) ? elog : -1e30f;
    float mx = lg;
#pragma unroll
    for (int off = 16; off > 0; off >>= 1)
        mx = fmaxf(mx, __shfl_xor_sync(FULL, mx, off));
    float a = (lane < KNN) ? __expf(lg - mx) : 0.f;
    float den = a;
#pragma unroll
    for (int off = 16; off > 0; off >>= 1)
        den += __shfl_xor_sync(FULL, den, off);
    float w = a / den;

    float vmx = w * (ecrel * relx + ecvel * vsx);
    float vmy = w * (ecrel * rely + ecvel * vsy);
    float vmz = w * (ecrel * relz + ecvel * vsz);
    float sg  = w * esmsg;
#pragma unroll
    for (int off = 16; off > 0; off >>= 1) {
        vmx += __shfl_xor_sync(FULL, vmx, off);
        vmy += __shfl_xor_sync(FULL, vmy, off);
        vmz += __shfl_xor_sync(FULL, vmz, off);
        sg  += __shfl_xor_sync(FULL, sg,  off);
    }

    float acc2 = 0.f;
#pragma unroll
    for (int qq = 0; qq < 2; qq++) {
        int j = lane + 32 * qq;
        float h = g_baseN[b][j];
        h = fmaf(mt, g_SN[j], h);
        h = fmaf(sg, Wn1[36 * 64 + j], h);
        acc2 = fmaf(gelu_fast(h), Wn2[j], acc2);
    }
#pragma unroll
    for (int off = 16; off > 0; off >>= 1)
        acc2 += __shfl_xor_sync(FULL, acc2, off);

    if (lane == 0) {
        float sout = acc2 + bn2[0];
        float al = alpha[0], be = beta[0];
        float* o = out + (size_t)warp * 7;
        o[0] = ptx + (ptx + al * vmx);
        o[1] = pty + (pty + al * vmy);
        o[2] = ptz + (ptz + al * vmz);
        o[3] = vtx + be * vmx;
        o[4] = vty + be * vmy;
        o[5] = vtz + be * vmz;
        o[6] = mt + sout;
    }
}

// ---------------- launch ----------------
extern "C" void kernel_launch(void* const* d_in, const int* in_sizes, int n_in,
                              void* d_out, int out_size)
{
    const float* z    = (const float*)d_in[0];
    const float* t    = (const float*)d_in[1];
    const float* cond = (const float*)d_in[2];
    const float* Wc1 = (const float*)d_in[4];
    const float* bc1 = (const float*)d_in[5];
    const float* Wc2 = (const float*)d_in[6];
    const float* bc2 = (const float*)d_in[7];
    const float* Wc3 = (const float*)d_in[8];
    const float* bc3 = (const float*)d_in[9];
    const float* We1 = (const float*)d_in[10];
    const float* be1 = (const float*)d_in[11];
    const float* We2 = (const float*)d_in[12];
    const float* be2 = (const float*)d_in[13];
    const float* Wn1 = (const float*)d_in[14];
    const float* bn1 = (const float*)d_in[15];
    const float* Wn2 = (const float*)d_in[16];
    const float* bn2 = (const float*)d_in[17];
    const float* alpha = (const float*)d_in[18];
    const float* beta  = (const float*)d_in[19];
    float* out = (float*)d_out;

    grid_bbox_kernel<<<NB, 256>>>(z);
    grid_count_kernel<<<NB * NPTS / 256, 256>>>(z);
    grid_scan_kernel<<<NB, 1024>>>();
    grid_scatter_kernel<<<NB * NPTS / 256, 256>>>(z);

    dim3 qg(NPTS / QPBQ, NB);
    knn_query_kernel<<<qg, QPBQ * QSPL>>>();

    setup_kernel<<<1, 256>>>(t, cond, Wc1, bc1, Wc2, bc2, Wc3, bc3,
                             We1, be1, Wn1, bn1);

    int total_warps = NB * NPTS;
    int blocks = total_warps / 8;
    main_kernel<<<blocks, 256>>>(z, We1, We2, be2, Wn1, Wn2, bn2,
                                 alpha, beta, out);
}

// round 9
// speedup vs baseline: 1.2962x; 1.2962x over previous
#include <cuda_runtime.h>
#include <math.h>
#include <limits.h>

#define NB   2
#define NPTS 8192
#define KNN  20
#define GDIM 16
#define G3   (GDIM*GDIM*GDIM)
#define CBUF 16

// ---------------- device scratch (no allocation allowed) ----------------
__device__ int    g_knn[NB * NPTS * KNN];
__device__ float  g_S1[128], g_S2[128], g_SN[64];
__device__ float  g_base1[NB][128];
__device__ float  g_baseN[NB][64];
// grid structures
__device__ float4 g_pts4[NB * NPTS];          // cell-sorted (x,y,z, 0.5*|p|^2)
__device__ int    g_ids [NB * NPTS];          // orig index per sorted slot
__device__ int    g_cellstart[NB * (G3 + 1)];
__device__ int    g_cnt[NB * G3];
__device__ float  g_lo[NB][3];
__device__ float  g_invs[NB][3];
__device__ float  g_cs[NB][3];                // cell sizes per axis

// exact-ish gelu (tanh via exp) for the tiny setup MLP
__device__ __forceinline__ float gelu_f(float x) {
    float y = 0.7978845608028654f * (x + 0.044715f * x * x * x);
    float e = __expf(2.0f * y);
    float th = 1.0f - 2.0f / (e + 1.0f);
    return 0.5f * x * (1.0f + th);
}

// fast gelu: tanh.approx.f32
__device__ __forceinline__ float gelu_fast(float x) {
    float y = 0.7978845608028654f * fmaf(0.044715f * x * x, x, x);
    float t;
    asm("tanh.approx.f32 %0, %1;" : "=f"(t) : "f"(y));
    return 0.5f * x * (1.0f + t);
}

__device__ __forceinline__ int cell_of(float v, float lo, float inv) {
    int i = (int)((v - lo) * inv);
    return i < 0 ? 0 : (i > GDIM - 1 ? GDIM - 1 : i);
}

// ---------------- grid kernel 1: zero counts + bbox (one block per batch) ----------------
__global__ __launch_bounds__(256) void grid_bbox_kernel(const float* __restrict__ z)
{
    const int b   = blockIdx.x;
    const int tid = threadIdx.x;
    const unsigned FULL = 0xffffffffu;

    for (int i = tid; i < G3; i += 256) g_cnt[b * G3 + i] = 0;

    float lx = 1e30f, ly = 1e30f, lz = 1e30f;
    float hx = -1e30f, hy = -1e30f, hz = -1e30f;
    const float* zb = z + (size_t)b * NPTS * 7;
    for (int n = tid; n < NPTS; n += 256) {
        const float* p = zb + (size_t)n * 7;
        float x = p[0], y = p[1], w = p[2];
        lx = fminf(lx, x); hx = fmaxf(hx, x);
        ly = fminf(ly, y); hy = fmaxf(hy, y);
        lz = fminf(lz, w); hz = fmaxf(hz, w);
    }
#pragma unroll
    for (int off = 16; off > 0; off >>= 1) {
        lx = fminf(lx, __shfl_xor_sync(FULL, lx, off));
        ly = fminf(ly, __shfl_xor_sync(FULL, ly, off));
        lz = fminf(lz, __shfl_xor_sync(FULL, lz, off));
        hx = fmaxf(hx, __shfl_xor_sync(FULL, hx, off));
        hy = fmaxf(hy, __shfl_xor_sync(FULL, hy, off));
        hz = fmaxf(hz, __shfl_xor_sync(FULL, hz, off));
    }
    __shared__ float slo[8][3], shi[8][3];
    const int warp = tid >> 5;
    if ((tid & 31) == 0) {
        slo[warp][0] = lx; slo[warp][1] = ly; slo[warp][2] = lz;
        shi[warp][0] = hx; shi[warp][1] = hy; shi[warp][2] = hz;
    }
    __syncthreads();
    if (tid == 0) {
        for (int w2 = 1; w2 < 8; w2++) {
            slo[0][0] = fminf(slo[0][0], slo[w2][0]);
            slo[0][1] = fminf(slo[0][1], slo[w2][1]);
            slo[0][2] = fminf(slo[0][2], slo[w2][2]);
            shi[0][0] = fmaxf(shi[0][0], shi[w2][0]);
            shi[0][1] = fmaxf(shi[0][1], shi[w2][1]);
            shi[0][2] = fmaxf(shi[0][2], shi[w2][2]);
        }
        for (int d = 0; d < 3; d++) {
            float span = fmaxf(shi[0][d] - slo[0][d], 1e-5f);
            g_lo[b][d]   = slo[0][d];
            g_invs[b][d] = (float)GDIM / span;
            g_cs[b][d]   = span / (float)GDIM;
        }
    }
}

// ---------------- grid kernel 2: count points per cell ----------------
__global__ __launch_bounds__(256) void grid_count_kernel(const float* __restrict__ z)
{
    int i = blockIdx.x * 256 + threadIdx.x;
    int b = i >> 13;
    int n = i & (NPTS - 1);
    const float* p = z + ((size_t)b * NPTS + n) * 7;
    int cx = cell_of(p[0], g_lo[b][0], g_invs[b][0]);
    int cy = cell_of(p[1], g_lo[b][1], g_invs[b][1]);
    int cz = cell_of(p[2], g_lo[b][2], g_invs[b][2]);
    atomicAdd(&g_cnt[b * G3 + (cx * GDIM + cy) * GDIM + cz], 1);
}

// ---------------- grid kernel 3: exclusive scan (one 1024-thr block per batch) ----------------
__global__ __launch_bounds__(1024) void grid_scan_kernel()
{
    __shared__ int sm[1024];
    const int b = blockIdx.x;
    const int t = threadIdx.x;
    const int base = t * (G3 / 1024);   // 4 cells per thread

    int sum = 0;
#pragma unroll
    for (int k = 0; k < G3 / 1024; k++) sum += g_cnt[b * G3 + base + k];
    sm[t] = sum;
    __syncthreads();
    for (int off = 1; off < 1024; off <<= 1) {
        int v = (t >= off) ? sm[t - off] : 0;
        __syncthreads();
        sm[t] += v;
        __syncthreads();
    }
    int running = sm[t] - sum;
#pragma unroll
    for (int k = 0; k < G3 / 1024; k++) {
        int c = base + k;
        int cc = g_cnt[b * G3 + c];
        g_cellstart[b * (G3 + 1) + c] = running;
        g_cnt[b * G3 + c] = running;
        running += cc;
    }
    if (t == 1023) g_cellstart[b * (G3 + 1) + G3] = running;
}

// ---------------- grid kernel 4: scatter into cell-sorted order ----------------
__global__ __launch_bounds__(256) void grid_scatter_kernel(const float* __restrict__ z)
{
    int i = blockIdx.x * 256 + threadIdx.x;
    int b = i >> 13;
    int n = i & (NPTS - 1);
    const float* p = z + ((size_t)b * NPTS + n) * 7;
    float x = p[0], y = p[1], w = p[2];
    int cx = cell_of(x, g_lo[b][0], g_invs[b][0]);
    int cy = cell_of(y, g_lo[b][1], g_invs[b][1]);
    int cz = cell_of(w, g_lo[b][2], g_invs[b][2]);
    int pos = atomicAdd(&g_cnt[b * G3 + (cx * GDIM + cy) * GDIM + cz], 1);
    g_pts4[b * NPTS + pos] = make_float4(x, y, w, 0.5f * (x * x + y * y + w * w));
    g_ids [b * NPTS + pos] = n;
}

// ---------------- grid kernel 5: warp-shared-region kNN ----------------
// One warp (= one 32-thread block) owns 32 consecutive cell-sorted queries.
// The warp scans expanding shells of the warp's shared cell bbox: the cell
// list is warp-uniform (no divergence) and every point is a broadcast LDG
// processed by all 32 queries in lockstep (R5 machinery: smem candidate
// buffer + ballot-batched sorted insert). Per-query exact stop bound =
// distance to the inflated-bbox boundary. score = 0.5|p|^2 - q.p.
__global__ __launch_bounds__(32) void knn_query_kernel()
{
    __shared__ float2 cbuf[CBUF][32];   // 4 KB

    const unsigned FULL = 0xffffffffu;
    const int lane = threadIdx.x;
    const int b    = blockIdx.y;
    const int slot = blockIdx.x * 32 + lane;

    const float4* pts = g_pts4 + (size_t)b * NPTS;
    const int*    cs  = g_cellstart + (size_t)b * (G3 + 1);

    float4 q4 = pts[slot];
    const float qx = q4.x, qy = q4.y, qz = q4.z;
    const float qr2 = 2.0f * q4.w;

    int cx = cell_of(qx, g_lo[b][0], g_invs[b][0]);
    int cy = cell_of(qy, g_lo[b][1], g_invs[b][1]);
    int cz = cell_of(qz, g_lo[b][2], g_invs[b][2]);

    // warp bbox of query cells
    int gx0 = cx, gx1 = cx, gy0 = cy, gy1 = cy, gz0 = cz, gz1 = cz;
#pragma unroll
    for (int off = 16; off > 0; off >>= 1) {
        gx0 = min(gx0, __shfl_xor_sync(FULL, gx0, off));
        gx1 = max(gx1, __shfl_xor_sync(FULL, gx1, off));
        gy0 = min(gy0, __shfl_xor_sync(FULL, gy0, off));
        gy1 = max(gy1, __shfl_xor_sync(FULL, gy1, off));
        gz0 = min(gz0, __shfl_xor_sync(FULL, gz0, off));
        gz1 = max(gz1, __shfl_xor_sync(FULL, gz1, off));
    }

    float bd[KNN];
    int   bi[KNN];
#pragma unroll
    for (int k = 0; k < KNN; k++) { bd[k] = 1e30f; bi[k] = -1; }

    float2* const wbase = &cbuf[0][lane];
    float2* const wtrig = &cbuf[CBUF - 8][lane];
    float2* wp = wbase;
    float tau = 1e30f;

#define COMPACT() do {                                                        \
    int cnt = (int)(wp - wbase) / 32;                                         \
    for (int i = 0; i < cnt; i++) {                                           \
        float2 c = cbuf[i][lane];                                             \
        float d = c.x;                                                        \
        if (d < bd[KNN - 1]) {                                                \
            int id = __float_as_int(c.y);                                     \
            _Pragma("unroll")                                                 \
            for (int k = KNN - 1; k > 0; --k) {                               \
                if (bd[k] > d) {                                              \
                    bool sh = bd[k - 1] > d;                                  \
                    bd[k] = sh ? bd[k - 1] : d;                               \
                    bi[k] = sh ? bi[k - 1] : id;                              \
                }                                                             \
            }                                                                 \
            if (bd[0] > d) { bd[0] = d; bi[0] = id; }                         \
        }                                                                     \
    }                                                                         \
    wp = wbase; tau = bd[KNN - 1];                                            \
} while (0)

#define SCAN_RANGE(ca, cb) do {                                               \
    int st = cs[ca];                                                          \
    int en = cs[(cb) + 1];                                                    \
    for (int j0 = st; j0 < en; j0 += 8) {                                     \
        int jend = min(j0 + 8, en);                                           \
        _Pragma("unroll")                                                     \
        for (int u = 0; u < 8; u++) {                                         \
            int j = j0 + u;                                                   \
            if (j < jend) {                                                   \
                float4 t4 = pts[j];                                           \
                float sv = fmaf(-qx, t4.x,                                    \
                           fmaf(-qy, t4.y, fmaf(-qz, t4.z, t4.w)));           \
                if (sv < tau && j != slot) {                                  \
                    *wp = make_float2(sv, __int_as_float(j));                 \
                    wp += 32;                                                 \
                }                                                             \
            }                                                                 \
        }                                                                     \
        if (__any_sync(FULL, wp >= wtrig)) COMPACT();                         \
    }                                                                         \
} while (0)

    int px0 = INT_MAX, px1 = INT_MIN, py0 = INT_MAX, py1 = INT_MIN;
    int pz0 = INT_MAX, pz1 = INT_MIN;

    for (int rho = 0; rho <= GDIM; rho++) {
        int X0 = max(gx0 - rho, 0), X1 = min(gx1 + rho, GDIM - 1);
        int Y0 = max(gy0 - rho, 0), Y1 = min(gy1 + rho, GDIM - 1);
        int Z0 = max(gz0 - rho, 0), Z1 = min(gz1 + rho, GDIM - 1);

        for (int ix = X0; ix <= X1; ix++) {
            for (int iy = Y0; iy <= Y1; iy++) {
                int cbase = (ix * GDIM + iy) * GDIM;
                bool fullz = (ix < px0) | (ix > px1) | (iy < py0) | (iy > py1);
                if (fullz) {
                    SCAN_RANGE(cbase + Z0, cbase + Z1);
                } else {
                    if (pz0 > Z0) SCAN_RANGE(cbase + Z0, cbase + pz0 - 1);
                    if (pz1 < Z1) SCAN_RANGE(cbase + pz1 + 1, cbase + Z1);
                }
            }
        }
        COMPACT();

        // per-query distance to inflated-bbox boundary (inf at domain edges)
        float d2b = 1e30f;
        if (X0 > 0)        d2b = fminf(d2b, qx - (g_lo[b][0] + (float)X0 * g_cs[b][0]));
        if (X1 < GDIM - 1) d2b = fminf(d2b, (g_lo[b][0] + (float)(X1 + 1) * g_cs[b][0]) - qx);
        if (Y0 > 0)        d2b = fminf(d2b, qy - (g_lo[b][1] + (float)Y0 * g_cs[b][1]));
        if (Y1 < GDIM - 1) d2b = fminf(d2b, (g_lo[b][1] + (float)(Y1 + 1) * g_cs[b][1]) - qy);
        if (Z0 > 0)        d2b = fminf(d2b, qz - (g_lo[b][2] + (float)Z0 * g_cs[b][2]));
        if (Z1 < GDIM - 1) d2b = fminf(d2b, (g_lo[b][2] + (float)(Z1 + 1) * g_cs[b][2]) - qz);

        bool done = (2.0f * bd[KNN - 1] + qr2) <= d2b * d2b * 0.998f;
        bool full = (X0 == 0 && Y0 == 0 && Z0 == 0 &&
                     X1 == GDIM - 1 && Y1 == GDIM - 1 && Z1 == GDIM - 1);
        if (full || __all_sync(FULL, done)) break;
        px0 = X0; px1 = X1; py0 = Y0; py1 = Y1; pz0 = Z0; pz1 = Z1;
    }
#undef SCAN_RANGE
#undef COMPACT

    const int* ids = g_ids + (size_t)b * NPTS;
    int* o = g_knn + ((size_t)b * NPTS + ids[slot]) * KNN;
#pragma unroll
    for (int k = 0; k < KNN; k++) o[k] = ids[bi[k]];
}

// ---------------- kernel: cond MLP + folded per-batch vectors ----------------
__global__ __launch_bounds__(256) void setup_kernel(
    const float* __restrict__ t, const float* __restrict__ conditioning,
    const float* __restrict__ Wc1, const float* __restrict__ bc1,
    const float* __restrict__ Wc2, const float* __restrict__ bc2,
    const float* __restrict__ Wc3, const float* __restrict__ bc3,
    const float* __restrict__ We1, const float* __restrict__ be1,
    const float* __restrict__ Wn1, const float* __restrict__ bn1)
{
    const unsigned FULL = 0xffffffffu;
    const int tid  = threadIdx.x;
    const int lane = tid & 31;
    const int warp = tid >> 5;

    if (tid < 128) {
        float s1 = 0.f, s2 = 0.f;
#pragma unroll
        for (int c = 0; c < 36; c++) {
            s1 += We1[c * 128 + tid];
            s2 += We1[(36 + c) * 128 + tid];
        }
        g_S1[tid] = s1;
        g_S2[tid] = s2;
    }
    if (tid < 64) {
        float sn = 0.f;
#pragma unroll
        for (int c = 0; c < 36; c++) sn += Wn1[c * 64 + tid];
        g_SN[tid] = sn;
    }

    __shared__ float sc[36], h1[144], h2[144], cv[40];

    for (int b = 0; b < NB; b++) {
        if (tid < 36) {
            float v;
            if (tid < 16) {
                float f = expf(-logf(10000.0f) * (float)tid / 15.0f);
                v = sinf(t[b] * f);
            } else if (tid < 32) {
                int i = tid - 16;
                float f = expf(-logf(10000.0f) * (float)i / 15.0f);
                v = cosf(t[b] * f);
            } else {
                v = conditioning[b * 4 + (tid - 32)];
            }
            sc[tid] = v;
        }
        __syncthreads();
        if (tid < 144) {
            float a = bc1[tid];
#pragma unroll
            for (int c = 0; c < 36; c++) a = fmaf(sc[c], Wc1[c * 144 + tid], a);
            h1[tid] = gelu_f(a);
        }
        __syncthreads();
        for (int o = 0; o < 18; o++) {
            int j = warp + 8 * o;
            float a = 0.f;
#pragma unroll
            for (int r = 0; r < 5; r++) {
                int c = lane + 32 * r;
                if (c < 144) a = fmaf(h1[c], Wc2[c * 144 + j], a);
            }
#pragma unroll
            for (int off = 16; off > 0; off >>= 1)
                a += __shfl_xor_sync(FULL, a, off);
            if (lane == 0) h2[j] = gelu_f(a + bc2[j]);
        }
        __syncthreads();
        for (int o = 0; o < 5; o++) {
            int j = warp + 8 * o;
            if (j < 36) {
                float a = 0.f;
#pragma unroll
                for (int r = 0; r < 5; r++) {
                    int c = lane + 32 * r;
                    if (c < 144) a = fmaf(h2[c], Wc3[c * 36 + j], a);
                }
#pragma unroll
                for (int off = 16; off > 0; off >>= 1)
                    a += __shfl_xor_sync(FULL, a, off);
                if (lane == 0) cv[j] = a + bc3[j];
            }
        }
        __syncthreads();
        if (tid < 128) {
            float a = be1[tid];
#pragma unroll
            for (int c = 0; c < 36; c++)
                a = fmaf(cv[c], We1[c * 128 + tid] + We1[(36 + c) * 128 + tid], a);
            g_base1[b][tid] = a;
        }
        if (tid < 64) {
            float a = bn1[tid];
#pragma unroll
            for (int c = 0; c < 36; c++) a = fmaf(cv[c], Wn1[c * 64 + tid], a);
            g_baseN[b][tid] = a;
        }
        __syncthreads();
    }
}

// ---------------- kernel: edge MLP + softmax + aggregation + node MLP ----------------
__global__ __launch_bounds__(256) void main_kernel(
    const float* __restrict__ z,
    const float* __restrict__ We1, const float* __restrict__ We2,
    const float* __restrict__ be2,
    const float* __restrict__ Wn1, const float* __restrict__ Wn2,
    const float* __restrict__ bn2,
    const float* __restrict__ alpha, const float* __restrict__ beta,
    float* __restrict__ out)
{
    __shared__ float4 part[8][KNN][17];

    const unsigned FULL = 0xffffffffu;
    const int wlocal = threadIdx.x >> 5;
    const int warp = (blockIdx.x * blockDim.x + threadIdx.x) >> 5;
    const int lane = threadIdx.x & 31;
    const int b = warp >> 13;
    const int n = warp & (NPTS - 1);

    const float* zb = z + (size_t)b * NPTS * 7;
    const float* zt = zb + (size_t)n * 7;
    const float ptx = zt[0], pty = zt[1], ptz = zt[2];
    const float vtx = zt[3], vty = zt[4], vtz = zt[5];
    const float mt  = zt[6];

    float relx = 0.f, rely = 0.f, relz = 0.f;
    float vsx = 0.f, vsy = 0.f, vsz = 0.f;
    float msrc = 0.f, r2 = 0.f, dvv = 0.f, dvr = 0.f, dtr = 0.f;
    if (lane < KNN) {
        int src = g_knn[(size_t)warp * KNN + lane];
        const float* zs = zb + (size_t)src * 7;
        float sx = zs[0], sy = zs[1], sz = zs[2];
        vsx = zs[3]; vsy = zs[4]; vsz = zs[5]; msrc = zs[6];
        relx = sx - ptx; rely = sy - pty; relz = sz - ptz;
        r2  = relx * relx + rely * rely + relz * relz;
        dvv = vsx * vtx + vsy * vty + vsz * vtz;
        dvr = vsx * relx + vsy * rely + vsz * relz;
        dtr = vtx * relx + vty * rely + vtz * relz;
    }

    float s1[4], s2[4], w72[4], w73[4], w74[4], w75[4], b1[4];
    float4 we2[4];
#pragma unroll
    for (int qq = 0; qq < 4; qq++) {
        int j = lane + 32 * qq;
        s1[qq]  = g_S1[j];
        s2[qq]  = g_S2[j];
        w72[qq] = We1[72 * 128 + j];
        w73[qq] = We1[73 * 128 + j];
        w74[qq] = We1[74 * 128 + j];
        w75[qq] = We1[75 * 128 + j];
        b1[qq]  = g_base1[b][j];
        we2[qq] = ((const float4*)We2)[j];
    }

#pragma unroll
    for (int e = 0; e < KNN; e++) {
        float em   = __shfl_sync(FULL, msrc, e);
        float er2  = __shfl_sync(FULL, r2,   e);
        float edvv = __shfl_sync(FULL, dvv,  e);
        float edvr = __shfl_sync(FULL, dvr,  e);
        float edtr = __shfl_sync(FULL, dtr,  e);
        float p0 = 0.f, p1 = 0.f, p2 = 0.f, p3 = 0.f;
#pragma unroll
        for (int qq = 0; qq < 4; qq++) {
            float h = b1[qq];
            h = fmaf(em,   s1[qq],  h);
            h = fmaf(mt,   s2[qq],  h);
            h = fmaf(er2,  w72[qq], h);
            h = fmaf(edvv, w73[qq], h);
            h = fmaf(edvr, w74[qq], h);
            h = fmaf(edtr, w75[qq], h);
            float g = gelu_fast(h);
            p0 = fmaf(g, we2[qq].x, p0);
            p1 = fmaf(g, we2[qq].y, p1);
            p2 = fmaf(g, we2[qq].z, p2);
            p3 = fmaf(g, we2[qq].w, p3);
        }
        p0 += __shfl_xor_sync(FULL, p0, 16);
        p1 += __shfl_xor_sync(FULL, p1, 16);
        p2 += __shfl_xor_sync(FULL, p2, 16);
        p3 += __shfl_xor_sync(FULL, p3, 16);
        if (lane < 16) part[wlocal][e][lane] = make_float4(p0, p1, p2, p3);
    }
    __syncwarp();

    float elog = -1e30f, esmsg = 0.f, ecrel = 0.f, ecvel = 0.f;
    if (lane < KNN) {
        float4 acc = part[wlocal][lane][0];
#pragma unroll
        for (int i = 1; i < 16; i++) {
            float4 p = part[wlocal][lane][i];
            acc.x += p.x; acc.y += p.y; acc.z += p.z; acc.w += p.w;
        }
        elog  = acc.x + be2[0];
        esmsg = acc.y + be2[1];
        ecrel = acc.z + be2[2];
        ecvel = acc.w + be2[3];
    }

    float lg = (lane < KNN) ? elog : -1e30f;
    float mx = lg;
#pragma unroll
    for (int off = 16; off > 0; off >>= 1)
        mx = fmaxf(mx, __shfl_xor_sync(FULL, mx, off));
    float a = (lane < KNN) ? __expf(lg - mx) : 0.f;
    float den = a;
#pragma unroll
    for (int off = 16; off > 0; off >>= 1)
        den += __shfl_xor_sync(FULL, den, off);
    float w = a / den;

    float vmx = w * (ecrel * relx + ecvel * vsx);
    float vmy = w * (ecrel * rely + ecvel * vsy);
    float vmz = w * (ecrel * relz + ecvel * vsz);
    float sg  = w * esmsg;
#pragma unroll
    for (int off = 16; off > 0; off >>= 1) {
        vmx += __shfl_xor_sync(FULL, vmx, off);
        vmy += __shfl_xor_sync(FULL, vmy, off);
        vmz += __shfl_xor_sync(FULL, vmz, off);
        sg  += __shfl_xor_sync(FULL, sg,  off);
    }

    float acc2 = 0.f;
#pragma unroll
    for (int qq = 0; qq < 2; qq++) {
        int j = lane + 32 * qq;
        float h = g_baseN[b][j];
        h = fmaf(mt, g_SN[j], h);
        h = fmaf(sg, Wn1[36 * 64 + j], h);
        acc2 = fmaf(gelu_fast(h), Wn2[j], acc2);
    }
#pragma unroll
    for (int off = 16; off > 0; off >>= 1)
        acc2 += __shfl_xor_sync(FULL, acc2, off);

    if (lane == 0) {
        float sout = acc2 + bn2[0];
        float al = alpha[0], be = beta[0];
        float* o = out + (size_t)warp * 7;
        o[0] = ptx + (ptx + al * vmx);
        o[1] = pty + (pty + al * vmy);
        o[2] = ptz + (ptz + al * vmz);
        o[3] = vtx + be * vmx;
        o[4] = vty + be * vmy;
        o[5] = vtz + be * vmz;
        o[6] = mt + sout;
    }
}

// ---------------- launch ----------------
extern "C" void kernel_launch(void* const* d_in, const int* in_sizes, int n_in,
                              void* d_out, int out_size)
{
    const float* z    = (const float*)d_in[0];
    const float* t    = (const float*)d_in[1];
    const float* cond = (const float*)d_in[2];
    const float* Wc1 = (const float*)d_in[4];
    const float* bc1 = (const float*)d_in[5];
    const float* Wc2 = (const float*)d_in[6];
    const float* bc2 = (const float*)d_in[7];
    const float* Wc3 = (const float*)d_in[8];
    const float* bc3 = (const float*)d_in[9];
    const float* We1 = (const float*)d_in[10];
    const float* be1 = (const float*)d_in[11];
    const float* We2 = (const float*)d_in[12];
    const float* be2 = (const float*)d_in[13];
    const float* Wn1 = (const float*)d_in[14];
    const float* bn1 = (const float*)d_in[15];
    const float* Wn2 = (const float*)d_in[16];
    const float* bn2 = (const float*)d_in[17];
    const float* alpha = (const float*)d_in[18];
    const float* beta  = (const float*)d_in[19];
    float* out = (float*)d_out;

    grid_bbox_kernel<<<NB, 256>>>(z);
    grid_count_kernel<<<NB * NPTS / 256, 256>>>(z);
    grid_scan_kernel<<<NB, 1024>>>();
    grid_scatter_kernel<<<NB * NPTS / 256, 256>>>(z);

    dim3 qg(NPTS / 32, NB);
    knn_query_kernel<<<qg, 32>>>();

    setup_kernel<<<1, 256>>>(t, cond, Wc1, bc1, Wc2, bc2, Wc3, bc3,
                             We1, be1, Wn1, bn1);

    int total_warps = NB * NPTS;
    int blocks = total_warps / 8;
    main_kernel<<<blocks, 256>>>(z, We1, We2, be2, Wn1, Wn2, bn2,
                                 alpha, beta, out);
}

// round 10
// speedup vs baseline: 3.1849x; 2.4572x over previous
#include <cuda_runtime.h>
#include <math.h>
#include <limits.h>

#define NB   2
#define NPTS 8192
#define KNN  20
#define GDIM 16
#define G3   (GDIM*GDIM*GDIM)
#define CBUF 16
#define QW   4        // point-split warps per query group
#define QT   (32*QW)  // 128 threads per query block

// ---------------- device scratch (no allocation allowed) ----------------
__device__ int    g_knn[NB * NPTS * KNN];
__device__ float  g_S1[128], g_S2[128], g_SN[64];
__device__ float  g_base1[NB][128];
__device__ float  g_baseN[NB][64];
// grid structures
__device__ float4 g_pts4[NB * NPTS];          // cell-sorted (x,y,z, 0.5*|p|^2)
__device__ int    g_ids [NB * NPTS];          // orig index per sorted slot
__device__ int    g_cellstart[NB * (G3 + 1)];
__device__ int    g_cnt[NB * G3];
__device__ float  g_lo[NB][3];
__device__ float  g_invs[NB][3];
__device__ float  g_cs[NB][3];

// exact-ish gelu (tanh via exp) for the tiny setup MLP
__device__ __forceinline__ float gelu_f(float x) {
    float y = 0.7978845608028654f * (x + 0.044715f * x * x * x);
    float e = __expf(2.0f * y);
    float th = 1.0f - 2.0f / (e + 1.0f);
    return 0.5f * x * (1.0f + th);
}

// fast gelu: tanh.approx.f32
__device__ __forceinline__ float gelu_fast(float x) {
    float y = 0.7978845608028654f * fmaf(0.044715f * x * x, x, x);
    float t;
    asm("tanh.approx.f32 %0, %1;" : "=f"(t) : "f"(y));
    return 0.5f * x * (1.0f + t);
}

__device__ __forceinline__ int cell_of(float v, float lo, float inv) {
    int i = (int)((v - lo) * inv);
    return i < 0 ? 0 : (i > GDIM - 1 ? GDIM - 1 : i);
}

// ---------------- grid kernel 1: zero counts + bbox (one block per batch) ----------------
__global__ __launch_bounds__(256) void grid_bbox_kernel(const float* __restrict__ z)
{
    const int b   = blockIdx.x;
    const int tid = threadIdx.x;
    const unsigned FULL = 0xffffffffu;

    for (int i = tid; i < G3; i += 256) g_cnt[b * G3 + i] = 0;

    float lx = 1e30f, ly = 1e30f, lz = 1e30f;
    float hx = -1e30f, hy = -1e30f, hz = -1e30f;
    const float* zb = z + (size_t)b * NPTS * 7;
    for (int n = tid; n < NPTS; n += 256) {
        const float* p = zb + (size_t)n * 7;
        float x = p[0], y = p[1], w = p[2];
        lx = fminf(lx, x); hx = fmaxf(hx, x);
        ly = fminf(ly, y); hy = fmaxf(hy, y);
        lz = fminf(lz, w); hz = fmaxf(hz, w);
    }
#pragma unroll
    for (int off = 16; off > 0; off >>= 1) {
        lx = fminf(lx, __shfl_xor_sync(FULL, lx, off));
        ly = fminf(ly, __shfl_xor_sync(FULL, ly, off));
        lz = fminf(lz, __shfl_xor_sync(FULL, lz, off));
        hx = fmaxf(hx, __shfl_xor_sync(FULL, hx, off));
        hy = fmaxf(hy, __shfl_xor_sync(FULL, hy, off));
        hz = fmaxf(hz, __shfl_xor_sync(FULL, hz, off));
    }
    __shared__ float slo[8][3], shi[8][3];
    const int warp = tid >> 5;
    if ((tid & 31) == 0) {
        slo[warp][0] = lx; slo[warp][1] = ly; slo[warp][2] = lz;
        shi[warp][0] = hx; shi[warp][1] = hy; shi[warp][2] = hz;
    }
    __syncthreads();
    if (tid == 0) {
        for (int w2 = 1; w2 < 8; w2++) {
            slo[0][0] = fminf(slo[0][0], slo[w2][0]);
            slo[0][1] = fminf(slo[0][1], slo[w2][1]);
            slo[0][2] = fminf(slo[0][2], slo[w2][2]);
            shi[0][0] = fmaxf(shi[0][0], shi[w2][0]);
            shi[0][1] = fmaxf(shi[0][1], shi[w2][1]);
            shi[0][2] = fmaxf(shi[0][2], shi[w2][2]);
        }
        for (int d = 0; d < 3; d++) {
            float span = fmaxf(shi[0][d] - slo[0][d], 1e-5f);
            g_lo[b][d]   = slo[0][d];
            g_invs[b][d] = (float)GDIM / span;
            g_cs[b][d]   = span / (float)GDIM;
        }
    }
}

// ---------------- grid kernel 2: count points per cell ----------------
__global__ __launch_bounds__(256) void grid_count_kernel(const float* __restrict__ z)
{
    int i = blockIdx.x * 256 + threadIdx.x;
    int b = i >> 13;
    int n = i & (NPTS - 1);
    const float* p = z + ((size_t)b * NPTS + n) * 7;
    int cx = cell_of(p[0], g_lo[b][0], g_invs[b][0]);
    int cy = cell_of(p[1], g_lo[b][1], g_invs[b][1]);
    int cz = cell_of(p[2], g_lo[b][2], g_invs[b][2]);
    atomicAdd(&g_cnt[b * G3 + (cx * GDIM + cy) * GDIM + cz], 1);
}

// ---------------- grid kernel 3: exclusive scan (one 1024-thr block per batch) ----------------
__global__ __launch_bounds__(1024) void grid_scan_kernel()
{
    __shared__ int sm[1024];
    const int b = blockIdx.x;
    const int t = threadIdx.x;
    const int base = t * (G3 / 1024);

    int sum = 0;
#pragma unroll
    for (int k = 0; k < G3 / 1024; k++) sum += g_cnt[b * G3 + base + k];
    sm[t] = sum;
    __syncthreads();
    for (int off = 1; off < 1024; off <<= 1) {
        int v = (t >= off) ? sm[t - off] : 0;
        __syncthreads();
        sm[t] += v;
        __syncthreads();
    }
    int running = sm[t] - sum;
#pragma unroll
    for (int k = 0; k < G3 / 1024; k++) {
        int c = base + k;
        int cc = g_cnt[b * G3 + c];
        g_cellstart[b * (G3 + 1) + c] = running;
        g_cnt[b * G3 + c] = running;
        running += cc;
    }
    if (t == 1023) g_cellstart[b * (G3 + 1) + G3] = running;
}

// ---------------- grid kernel 4: scatter into cell-sorted order ----------------
__global__ __launch_bounds__(256) void grid_scatter_kernel(const float* __restrict__ z)
{
    int i = blockIdx.x * 256 + threadIdx.x;
    int b = i >> 13;
    int n = i & (NPTS - 1);
    const float* p = z + ((size_t)b * NPTS + n) * 7;
    float x = p[0], y = p[1], w = p[2];
    int cx = cell_of(x, g_lo[b][0], g_invs[b][0]);
    int cy = cell_of(y, g_lo[b][1], g_invs[b][1]);
    int cz = cell_of(w, g_lo[b][2], g_invs[b][2]);
    int pos = atomicAdd(&g_cnt[b * G3 + (cx * GDIM + cy) * GDIM + cz], 1);
    g_pts4[b * NPTS + pos] = make_float4(x, y, w, 0.5f * (x * x + y * y + w * w));
    g_ids [b * NPTS + pos] = n;
}

// ---------------- grid kernel 5: warp-shared-region kNN, 4 point-split warps ----------------
// Block = 32 cell-sorted queries x 4 warps. All warps hold the same 32
// queries (lane = query) and enumerate identical shell ranges of the group's
// cell bbox; they deal 8-point chunks round-robin. Per-warp top-20 + smem
// candidate buffer + ballot compaction + shared tau (benign fmin race).
// Stop: union-20th <= min over warps of per-warp 20th, vs distance to the
// inflated bbox boundary; block-uniform break. score = 0.5|p|^2 - q.p.
__global__ __launch_bounds__(QT) void knn_query_kernel()
{
    __shared__ float2 cbuf[CBUF][QT];          // 16 KB
    __shared__ float  tau_sh[32];
    __shared__ float  bd19[QW][32];
    __shared__ float2 mg[32][QW * KNN + 1];    // padded: 2-way conflicts max

    const unsigned FULL = 0xffffffffu;
    const int tid  = threadIdx.x;
    const int lane = tid & 31;                 // query
    const int w    = tid >> 5;                 // point-split warp
    const int b    = blockIdx.y;
    const int slot = blockIdx.x * 32 + lane;

    const float4* pts = g_pts4 + (size_t)b * NPTS;
    const int*    cs  = g_cellstart + (size_t)b * (G3 + 1);

    float4 q4 = pts[slot];
    const float qx = q4.x, qy = q4.y, qz = q4.z;
    const float qr2 = 2.0f * q4.w;

    int cx = cell_of(qx, g_lo[b][0], g_invs[b][0]);
    int cy = cell_of(qy, g_lo[b][1], g_invs[b][1]);
    int cz = cell_of(qz, g_lo[b][2], g_invs[b][2]);

    // group bbox of query cells (identical in every warp)
    int gx0 = cx, gx1 = cx, gy0 = cy, gy1 = cy, gz0 = cz, gz1 = cz;
#pragma unroll
    for (int off = 16; off > 0; off >>= 1) {
        gx0 = min(gx0, __shfl_xor_sync(FULL, gx0, off));
        gx1 = max(gx1, __shfl_xor_sync(FULL, gx1, off));
        gy0 = min(gy0, __shfl_xor_sync(FULL, gy0, off));
        gy1 = max(gy1, __shfl_xor_sync(FULL, gy1, off));
        gz0 = min(gz0, __shfl_xor_sync(FULL, gz0, off));
        gz1 = max(gz1, __shfl_xor_sync(FULL, gz1, off));
    }

    if (tid < 32) tau_sh[tid] = 1e30f;
    __syncthreads();

    float bd[KNN];
    int   bi[KNN];
#pragma unroll
    for (int k = 0; k < KNN; k++) { bd[k] = 1e30f; bi[k] = -1; }

    float2* const wbase = &cbuf[0][tid];
    float2* const wtrig = &cbuf[CBUF - 8][tid];
    float2* wp = wbase;
    float tau = 1e30f;

#define COMPACT() do {                                                        \
    int cnt = (int)(wp - wbase) / QT;                                         \
    for (int i = 0; i < cnt; i++) {                                           \
        float2 c = cbuf[i][tid];                                              \
        float d = c.x;                                                        \
        if (d < bd[KNN - 1]) {                                                \
            int id = __float_as_int(c.y);                                     \
            _Pragma("unroll")                                                 \
            for (int k = KNN - 1; k > 0; --k) {                               \
                if (bd[k] > d) {                                              \
                    bool sh = bd[k - 1] > d;                                  \
                    bd[k] = sh ? bd[k - 1] : d;                               \
                    bi[k] = sh ? bi[k - 1] : id;                              \
                }                                                             \
            }                                                                 \
            if (bd[0] > d) { bd[0] = d; bi[0] = id; }                         \
        }                                                                     \
    }                                                                         \
    wp = wbase;                                                               \
    tau_sh[lane] = fminf(tau_sh[lane], bd[KNN - 1]);                          \
    tau = fminf(bd[KNN - 1], tau_sh[lane]);                                   \
} while (0)

#define SCAN_RANGE(ca, cb) do {                                               \
    int st = cs[ca];                                                          \
    int en = cs[(cb) + 1];                                                    \
    for (int j0 = st + 8 * w; j0 < en; j0 += 8 * QW) {                        \
        int jend = min(j0 + 8, en);                                           \
        _Pragma("unroll")                                                     \
        for (int u = 0; u < 8; u++) {                                         \
            int j = j0 + u;                                                   \
            if (j < jend) {                                                   \
                float4 t4 = pts[j];                                           \
                float sv = fmaf(-qx, t4.x,                                    \
                           fmaf(-qy, t4.y, fmaf(-qz, t4.z, t4.w)));           \
                if (sv < tau && j != slot) {                                  \
                    *wp = make_float2(sv, __int_as_float(j));                 \
                    wp += QT;                                                 \
                }                                                             \
            }                                                                 \
        }                                                                     \
        if (__any_sync(FULL, wp >= wtrig)) COMPACT();                         \
    }                                                                         \
} while (0)

    int px0 = INT_MAX, px1 = INT_MIN, py0 = INT_MAX, py1 = INT_MIN;
    int pz0 = INT_MAX, pz1 = INT_MIN;

    for (int rho = 0; rho <= GDIM; rho++) {
        int X0 = max(gx0 - rho, 0), X1 = min(gx1 + rho, GDIM - 1);
        int Y0 = max(gy0 - rho, 0), Y1 = min(gy1 + rho, GDIM - 1);
        int Z0 = max(gz0 - rho, 0), Z1 = min(gz1 + rho, GDIM - 1);

        for (int ix = X0; ix <= X1; ix++) {
            for (int iy = Y0; iy <= Y1; iy++) {
                int cbase = (ix * GDIM + iy) * GDIM;
                bool fullz = (ix < px0) | (ix > px1) | (iy < py0) | (iy > py1);
                if (fullz) {
                    SCAN_RANGE(cbase + Z0, cbase + Z1);
                } else {
                    if (pz0 > Z0) SCAN_RANGE(cbase + Z0, cbase + pz0 - 1);
                    if (pz1 < Z1) SCAN_RANGE(cbase + pz1 + 1, cbase + Z1);
                }
            }
        }
        COMPACT();
        bd19[w][lane] = bd[KNN - 1];
        __syncthreads();

        // union-20th upper bound across the 4 split warps
        float ub = fminf(fminf(bd19[0][lane], bd19[1][lane]),
                         fminf(bd19[2][lane], bd19[3][lane]));

        // per-query distance to inflated-bbox boundary (inf at domain edges)
        float d2b = 1e30f;
        if (X0 > 0)        d2b = fminf(d2b, qx - (g_lo[b][0] + (float)X0 * g_cs[b][0]));
        if (X1 < GDIM - 1) d2b = fminf(d2b, (g_lo[b][0] + (float)(X1 + 1) * g_cs[b][0]) - qx);
        if (Y0 > 0)        d2b = fminf(d2b, qy - (g_lo[b][1] + (float)Y0 * g_cs[b][1]));
        if (Y1 < GDIM - 1) d2b = fminf(d2b, (g_lo[b][1] + (float)(Y1 + 1) * g_cs[b][1]) - qy);
        if (Z0 > 0)        d2b = fminf(d2b, qz - (g_lo[b][2] + (float)Z0 * g_cs[b][2]));
        if (Z1 < GDIM - 1) d2b = fminf(d2b, (g_lo[b][2] + (float)(Z1 + 1) * g_cs[b][2]) - qz);

        bool done = (2.0f * ub + qr2) <= d2b * d2b * 0.998f;
        bool full = (X0 == 0 && Y0 == 0 && Z0 == 0 &&
                     X1 == GDIM - 1 && Y1 == GDIM - 1 && Z1 == GDIM - 1);
        int alldone = __syncthreads_and(done ? 1 : 0);
        if (full || alldone) break;
        px0 = X0; px1 = X1; py0 = Y0; py1 = Y1; pz0 = Z0; pz1 = Z1;
    }
#undef SCAN_RANGE
#undef COMPACT

    // merge the 4 warps' top-20 per query
#pragma unroll
    for (int k = 0; k < KNN; k++)
        mg[lane][w * KNN + k] = make_float2(bd[k], __int_as_float(bi[k]));
    __syncthreads();

    if (w == 0) {
        float fd[KNN]; int fi[KNN];
#pragma unroll
        for (int k = 0; k < KNN; k++) { fd[k] = 1e30f; fi[k] = -1; }
        for (int i = 0; i < QW * KNN; i++) {
            float2 c = mg[lane][i];
            float d = c.x;
            if (d < fd[KNN - 1]) {
                int id = __float_as_int(c.y);
#pragma unroll
                for (int k = KNN - 1; k > 0; --k) {
                    if (fd[k] > d) {
                        bool sh = fd[k - 1] > d;
                        fd[k] = sh ? fd[k - 1] : d;
                        fi[k] = sh ? fi[k - 1] : id;
                    }
                }
                if (fd[0] > d) { fd[0] = d; fi[0] = id; }
            }
        }
        const int* ids = g_ids + (size_t)b * NPTS;
        int* o = g_knn + ((size_t)b * NPTS + ids[slot]) * KNN;
#pragma unroll
        for (int k = 0; k < KNN; k++) o[k] = ids[fi[k]];
    }
}

// ---------------- kernel: cond MLP + folded per-batch vectors ----------------
__global__ __launch_bounds__(256) void setup_kernel(
    const float* __restrict__ t, const float* __restrict__ conditioning,
    const float* __restrict__ Wc1, const float* __restrict__ bc1,
    const float* __restrict__ Wc2, const float* __restrict__ bc2,
    const float* __restrict__ Wc3, const float* __restrict__ bc3,
    const float* __restrict__ We1, const float* __restrict__ be1,
    const float* __restrict__ Wn1, const float* __restrict__ bn1)
{
    const unsigned FULL = 0xffffffffu;
    const int tid  = threadIdx.x;
    const int lane = tid & 31;
    const int warp = tid >> 5;

    if (tid < 128) {
        float s1 = 0.f, s2 = 0.f;
#pragma unroll
        for (int c = 0; c < 36; c++) {
            s1 += We1[c * 128 + tid];
            s2 += We1[(36 + c) * 128 + tid];
        }
        g_S1[tid] = s1;
        g_S2[tid] = s2;
    }
    if (tid < 64) {
        float sn = 0.f;
#pragma unroll
        for (int c = 0; c < 36; c++) sn += Wn1[c * 64 + tid];
        g_SN[tid] = sn;
    }

    __shared__ float sc[36], h1[144], h2[144], cv[40];

    for (int b = 0; b < NB; b++) {
        if (tid < 36) {
            float v;
            if (tid < 16) {
                float f = expf(-logf(10000.0f) * (float)tid / 15.0f);
                v = sinf(t[b] * f);
            } else if (tid < 32) {
                int i = tid - 16;
                float f = expf(-logf(10000.0f) * (float)i / 15.0f);
                v = cosf(t[b] * f);
            } else {
                v = conditioning[b * 4 + (tid - 32)];
            }
            sc[tid] = v;
        }
        __syncthreads();
        if (tid < 144) {
            float a = bc1[tid];
#pragma unroll
            for (int c = 0; c < 36; c++) a = fmaf(sc[c], Wc1[c * 144 + tid], a);
            h1[tid] = gelu_f(a);
        }
        __syncthreads();
        for (int o = 0; o < 18; o++) {
            int j = warp + 8 * o;
            float a = 0.f;
#pragma unroll
            for (int r = 0; r < 5; r++) {
                int c = lane + 32 * r;
                if (c < 144) a = fmaf(h1[c], Wc2[c * 144 + j], a);
            }
#pragma unroll
            for (int off = 16; off > 0; off >>= 1)
                a += __shfl_xor_sync(FULL, a, off);
            if (lane == 0) h2[j] = gelu_f(a + bc2[j]);
        }
        __syncthreads();
        for (int o = 0; o < 5; o++) {
            int j = warp + 8 * o;
            if (j < 36) {
                float a = 0.f;
#pragma unroll
                for (int r = 0; r < 5; r++) {
                    int c = lane + 32 * r;
                    if (c < 144) a = fmaf(h2[c], Wc3[c * 36 + j], a);
                }
#pragma unroll
                for (int off = 16; off > 0; off >>= 1)
                    a += __shfl_xor_sync(FULL, a, off);
                if (lane == 0) cv[j] = a + bc3[j];
            }
        }
        __syncthreads();
        if (tid < 128) {
            float a = be1[tid];
#pragma unroll
            for (int c = 0; c < 36; c++)
                a = fmaf(cv[c], We1[c * 128 + tid] + We1[(36 + c) * 128 + tid], a);
            g_base1[b][tid] = a;
        }
        if (tid < 64) {
            float a = bn1[tid];
#pragma unroll
            for (int c = 0; c < 36; c++) a = fmaf(cv[c], Wn1[c * 64 + tid], a);
            g_baseN[b][tid] = a;
        }
        __syncthreads();
    }
}

// ---------------- kernel: edge MLP + softmax + aggregation + node MLP ----------------
__global__ __launch_bounds__(256) void main_kernel(
    const float* __restrict__ z,
    const float* __restrict__ We1, const float* __restrict__ We2,
    const float* __restrict__ be2,
    const float* __restrict__ Wn1, const float* __restrict__ Wn2,
    const float* __restrict__ bn2,
    const float* __restrict__ alpha, const float* __restrict__ beta,
    float* __restrict__ out)
{
    __shared__ float4 part[8][KNN][17];

    const unsigned FULL = 0xffffffffu;
    const int wlocal = threadIdx.x >> 5;
    const int warp = (blockIdx.x * blockDim.x + threadIdx.x) >> 5;
    const int lane = threadIdx.x & 31;
    const int b = warp >> 13;
    const int n = warp & (NPTS - 1);

    const float* zb = z + (size_t)b * NPTS * 7;
    const float* zt = zb + (size_t)n * 7;
    const float ptx = zt[0], pty = zt[1], ptz = zt[2];
    const float vtx = zt[3], vty = zt[4], vtz = zt[5];
    const float mt  = zt[6];

    float relx = 0.f, rely = 0.f, relz = 0.f;
    float vsx = 0.f, vsy = 0.f, vsz = 0.f;
    float msrc = 0.f, r2 = 0.f, dvv = 0.f, dvr = 0.f, dtr = 0.f;
    if (lane < KNN) {
        int src = g_knn[(size_t)warp * KNN + lane];
        const float* zs = zb + (size_t)src * 7;
        float sx = zs[0], sy = zs[1], sz = zs[2];
        vsx = zs[3]; vsy = zs[4]; vsz = zs[5]; msrc = zs[6];
        relx = sx - ptx; rely = sy - pty; relz = sz - ptz;
        r2  = relx * relx + rely * rely + relz * relz;
        dvv = vsx * vtx + vsy * vty + vsz * vtz;
        dvr = vsx * relx + vsy * rely + vsz * relz;
        dtr = vtx * relx + vty * rely + vtz * relz;
    }

    float s1[4], s2[4], w72[4], w73[4], w74[4], w75[4], b1[4];
    float4 we2[4];
#pragma unroll
    for (int qq = 0; qq < 4; qq++) {
        int j = lane + 32 * qq;
        s1[qq]  = g_S1[j];
        s2[qq]  = g_S2[j];
        w72[qq] = We1[72 * 128 + j];
        w73[qq] = We1[73 * 128 + j];
        w74[qq] = We1[74 * 128 + j];
        w75[qq] = We1[75 * 128 + j];
        b1[qq]  = g_base1[b][j];
        we2[qq] = ((const float4*)We2)[j];
    }

#pragma unroll
    for (int e = 0; e < KNN; e++) {
        float em   = __shfl_sync(FULL, msrc, e);
        float er2  = __shfl_sync(FULL, r2,   e);
        float edvv = __shfl_sync(FULL, dvv,  e);
        float edvr = __shfl_sync(FULL, dvr,  e);
        float edtr = __shfl_sync(FULL, dtr,  e);
        float p0 = 0.f, p1 = 0.f, p2 = 0.f, p3 = 0.f;
#pragma unroll
        for (int qq = 0; qq < 4; qq++) {
            float h = b1[qq];
            h = fmaf(em,   s1[qq],  h);
            h = fmaf(mt,   s2[qq],  h);
            h = fmaf(er2,  w72[qq], h);
            h = fmaf(edvv, w73[qq], h);
            h = fmaf(edvr, w74[qq], h);
            h = fmaf(edtr, w75[qq], h);
            float g = gelu_fast(h);
            p0 = fmaf(g, we2[qq].x, p0);
            p1 = fmaf(g, we2[qq].y, p1);
            p2 = fmaf(g, we2[qq].z, p2);
            p3 = fmaf(g, we2[qq].w, p3);
        }
        p0 += __shfl_xor_sync(FULL, p0, 16);
        p1 += __shfl_xor_sync(FULL, p1, 16);
        p2 += __shfl_xor_sync(FULL, p2, 16);
        p3 += __shfl_xor_sync(FULL, p3, 16);
        if (lane < 16) part[wlocal][e][lane] = make_float4(p0, p1, p2, p3);
    }
    __syncwarp();

    float elog = -1e30f, esmsg = 0.f, ecrel = 0.f, ecvel = 0.f;
    if (lane < KNN) {
        float4 acc = part[wlocal][lane][0];
#pragma unroll
        for (int i = 1; i < 16; i++) {
            float4 p = part[wlocal][lane][i];
            acc.x += p.x; acc.y += p.y; acc.z += p.z; acc.w += p.w;
        }
        elog  = acc.x + be2[0];
        esmsg = acc.y + be2[1];
        ecrel = acc.z + be2[2];
        ecvel = acc.w + be2[3];
    }

    float lg = (lane < KNN) ? elog : -1e30f;
    float mx = lg;
#pragma unroll
    for (int off = 16; off > 0; off >>= 1)
        mx = fmaxf(mx, __shfl_xor_sync(FULL, mx, off));
    float a = (lane < KNN) ? __expf(lg - mx) : 0.f;
    float den = a;
#pragma unroll
    for (int off = 16; off > 0; off >>= 1)
        den += __shfl_xor_sync(FULL, den, off);
    float w = a / den;

    float vmx = w * (ecrel * relx + ecvel * vsx);
    float vmy = w * (ecrel * rely + ecvel * vsy);
    float vmz = w * (ecrel * relz + ecvel * vsz);
    float sg  = w * esmsg;
#pragma unroll
    for (int off = 16; off > 0; off >>= 1) {
        vmx += __shfl_xor_sync(FULL, vmx, off);
        vmy += __shfl_xor_sync(FULL, vmy, off);
        vmz += __shfl_xor_sync(FULL, vmz, off);
        sg  += __shfl_xor_sync(FULL, sg,  off);
    }

    float acc2 = 0.f;
#pragma unroll
    for (int qq = 0; qq < 2; qq++) {
        int j = lane + 32 * qq;
        float h = g_baseN[b][j];
        h = fmaf(mt, g_SN[j], h);
        h = fmaf(sg, Wn1[36 * 64 + j], h);
        acc2 = fmaf(gelu_fast(h), Wn2[j], acc2);
    }
#pragma unroll
    for (int off = 16; off > 0; off >>= 1)
        acc2 += __shfl_xor_sync(FULL, acc2, off);

    if (lane == 0) {
        float sout = acc2 + bn2[0];
        float al = alpha[0], be = beta[0];
        float* o = out + (size_t)warp * 7;
        o[0] = ptx + (ptx + al * vmx);
        o[1] = pty + (pty + al * vmy);
        o[2] = ptz + (ptz + al * vmz);
        o[3] = vtx + be * vmx;
        o[4] = vty + be * vmy;
        o[5] = vtz + be * vmz;
        o[6] = mt + sout;
    }
}

// ---------------- launch ----------------
extern "C" void kernel_launch(void* const* d_in, const int* in_sizes, int n_in,
                              void* d_out, int out_size)
{
    const float* z    = (const float*)d_in[0];
    const float* t    = (const float*)d_in[1];
    const float* cond = (const float*)d_in[2];
    const float* Wc1 = (const float*)d_in[4];
    const float* bc1 = (const float*)d_in[5];
    const float* Wc2 = (const float*)d_in[6];
    const float* bc2 = (const float*)d_in[7];
    const float* Wc3 = (const float*)d_in[8];
    const float* bc3 = (const float*)d_in[9];
    const float* We1 = (const float*)d_in[10];
    const float* be1 = (const float*)d_in[11];
    const float* We2 = (const float*)d_in[12];
    const float* be2 = (const float*)d_in[13];
    const float* Wn1 = (const float*)d_in[14];
    const float* bn1 = (const float*)d_in[15];
    const float* Wn2 = (const float*)d_in[16];
    const float* bn2 = (const float*)d_in[17];
    const float* alpha = (const float*)d_in[18];
    const float* beta  = (const float*)d_in[19];
    float* out = (float*)d_out;

    grid_bbox_kernel<<<NB, 256>>>(z);
    grid_count_kernel<<<NB * NPTS / 256, 256>>>(z);
    grid_scan_kernel<<<NB, 1024>>>();
    grid_scatter_kernel<<<NB * NPTS / 256, 256>>>(z);

    dim3 qg(NPTS / 32, NB);
    knn_query_kernel<<<qg, QT>>>();

    setup_kernel<<<1, 256>>>(t, cond, Wc1, bc1, Wc2, bc2, Wc3, bc3,
                             We1, be1, Wn1, bn1);

    int total_warps = NB * NPTS;
    int blocks = total_warps / 8;
    main_kernel<<<blocks, 256>>>(z, We1, We2, be2, Wn1, Wn2, bn2,
                                 alpha, beta, out);
}

// round 11
// speedup vs baseline: 6.2299x; 1.9561x over previous
#include <cuda_runtime.h>
#include <math.h>

#define NB   2
#define NPTS 8192
#define KNN  20
#define TILE 960         // float4 tile entries (15360 B)
#define QPB  32          // queries per knn block (= lanes)
#define NSPL 8           // point splits (= warps per knn block)
#define KTHR (QPB*NSPL)  // 256 threads
#define CBUF 16

// ---------------- device scratch (no allocation allowed) ----------------
__device__ int   g_knn[NB * NPTS * KNN];
__device__ float g_S1[128], g_S2[128], g_SN[64];
__device__ float g_base1[NB][128];
__device__ float g_baseN[NB][64];

// exact-ish gelu (tanh via exp) for the tiny setup MLP
__device__ __forceinline__ float gelu_f(float x) {
    float y = 0.7978845608028654f * (x + 0.044715f * x * x * x);
    float e = __expf(2.0f * y);
    float th = 1.0f - 2.0f / (e + 1.0f);
    return 0.5f * x * (1.0f + th);
}

// fast gelu: tanh.approx.f32
__device__ __forceinline__ float gelu_fast(float x) {
    float y = 0.7978845608028654f * fmaf(0.044715f * x * x, x, x);
    float t;
    asm("tanh.approx.f32 %0, %1;" : "=f"(t) : "f"(y));
    return 0.5f * x * (1.0f + t);
}

// ---------------- kernel 1: cond MLP + folded per-batch vectors ----------------
__global__ __launch_bounds__(256) void setup_kernel(
    const float* __restrict__ t, const float* __restrict__ conditioning,
    const float* __restrict__ Wc1, const float* __restrict__ bc1,
    const float* __restrict__ Wc2, const float* __restrict__ bc2,
    const float* __restrict__ Wc3, const float* __restrict__ bc3,
    const float* __restrict__ We1, const float* __restrict__ be1,
    const float* __restrict__ Wn1, const float* __restrict__ bn1)
{
    const unsigned FULL = 0xffffffffu;
    const int tid  = threadIdx.x;
    const int lane = tid & 31;
    const int warp = tid >> 5;

    if (tid < 128) {
        float s1 = 0.f, s2 = 0.f;
#pragma unroll
        for (int c = 0; c < 36; c++) {
            s1 += We1[c * 128 + tid];
            s2 += We1[(36 + c) * 128 + tid];
        }
        g_S1[tid] = s1;
        g_S2[tid] = s2;
    }
    if (tid < 64) {
        float sn = 0.f;
#pragma unroll
        for (int c = 0; c < 36; c++) sn += Wn1[c * 64 + tid];
        g_SN[tid] = sn;
    }

    __shared__ float sc[36], h1[144], h2[144], cv[40];

    for (int b = 0; b < NB; b++) {
        if (tid < 36) {
            float v;
            if (tid < 16) {
                float f = expf(-logf(10000.0f) * (float)tid / 15.0f);
                v = sinf(t[b] * f);
            } else if (tid < 32) {
                int i = tid - 16;
                float f = expf(-logf(10000.0f) * (float)i / 15.0f);
                v = cosf(t[b] * f);
            } else {
                v = conditioning[b * 4 + (tid - 32)];
            }
            sc[tid] = v;
        }
        __syncthreads();
        if (tid < 144) {
            float a = bc1[tid];
#pragma unroll
            for (int c = 0; c < 36; c++) a = fmaf(sc[c], Wc1[c * 144 + tid], a);
            h1[tid] = gelu_f(a);
        }
        __syncthreads();
        for (int o = 0; o < 18; o++) {
            int j = warp + 8 * o;
            float a = 0.f;
#pragma unroll
            for (int r = 0; r < 5; r++) {
                int c = lane + 32 * r;
                if (c < 144) a = fmaf(h1[c], Wc2[c * 144 + j], a);
            }
#pragma unroll
            for (int off = 16; off > 0; off >>= 1)
                a += __shfl_xor_sync(FULL, a, off);
            if (lane == 0) h2[j] = gelu_f(a + bc2[j]);
        }
        __syncthreads();
        for (int o = 0; o < 5; o++) {
            int j = warp + 8 * o;
            if (j < 36) {
                float a = 0.f;
#pragma unroll
                for (int r = 0; r < 5; r++) {
                    int c = lane + 32 * r;
                    if (c < 144) a = fmaf(h2[c], Wc3[c * 36 + j], a);
                }
#pragma unroll
                for (int off = 16; off > 0; off >>= 1)
                    a += __shfl_xor_sync(FULL, a, off);
                if (lane == 0) cv[j] = a + bc3[j];
            }
        }
        __syncthreads();
        if (tid < 128) {
            float a = be1[tid];
#pragma unroll
            for (int c = 0; c < 36; c++)
                a = fmaf(cv[c], We1[c * 128 + tid] + We1[(36 + c) * 128 + tid], a);
            g_base1[b][tid] = a;
        }
        if (tid < 64) {
            float a = bn1[tid];
#pragma unroll
            for (int c = 0; c < 36; c++) a = fmaf(cv[c], Wn1[c * 64 + tid], a);
            g_baseN[b][tid] = a;
        }
        __syncthreads();
    }
}

// ---------------- kernel 2: brute-force kNN (R5 structure, 8 splits) ----------------
// 256 threads = 32 queries x 8 point-splits. Warp = split, lanes = queries
// (tile reads are warp-broadcast). SMEM candidate buffer with 32-bit
// cnt-indexed append (R5 codegen — NOT the R6 pointer-bump), ballot-batched
// compaction, shared per-query tau upper bound (benign non-atomic fmin race).
// score = 0.5*|p|^2 - q.p  (monotone in d2 for fixed query).
__global__ __launch_bounds__(KTHR) void knn_kernel(const float* __restrict__ z)
{
    // scan phase: tile (15360 B) + cbuf (32768 B) = 48128 B
    // merge phase: md (20480 B) + mi (20480 B)   = 40960 B  (same union)
    __shared__ __align__(16) unsigned char raw[48128];
    __shared__ float tau_sh[QPB];
    float4* tile4 = (float4*)raw;
    float2 (*cbuf)[KTHR] = (float2 (*)[KTHR])(raw + TILE * 16);

    const unsigned FULL = 0xffffffffu;
    const int tid = threadIdx.x;
    const int b   = blockIdx.y;
    const int lq  = tid & 31;                 // query lane
    const int s   = tid >> 5;                 // split = warp
    const int q   = blockIdx.x * QPB + lq;

    const float* zb = z + (size_t)b * NPTS * 7;
    const float* zq = zb + (size_t)q * 7;
    const float qx = zq[0], qy = zq[1], qz = zq[2];

    if (tid < QPB) tau_sh[tid] = 1e30f;

    float bd[KNN];
    int   bi[KNN];
#pragma unroll
    for (int k = 0; k < KNN; k++) { bd[k] = 1e30f; bi[k] = -1; }

    int   cnt = 0;
    float tau = 1e30f;

#define COMPACT() do {                                                        \
    for (int i = 0; i < cnt; i++) {                                           \
        float2 c = cbuf[i][tid];                                              \
        float d = c.x;                                                        \
        int  id = __float_as_int(c.y);                                        \
        if (d < bd[KNN - 1] && id != q) {                                     \
            _Pragma("unroll")                                                 \
            for (int k = KNN - 1; k > 0; --k) {                               \
                if (bd[k] > d) {                                              \
                    bool sh = bd[k - 1] > d;                                  \
                    bd[k] = sh ? bd[k - 1] : d;                               \
                    bi[k] = sh ? bi[k - 1] : id;                              \
                }                                                             \
            }                                                                 \
            if (bd[0] > d) { bd[0] = d; bi[0] = id; }                         \
        }                                                                     \
    }                                                                         \
    cnt = 0;                                                                  \
    tau_sh[lq] = fminf(tau_sh[lq], bd[KNN - 1]);                              \
    tau = fminf(bd[KNN - 1], tau_sh[lq]);                                     \
} while (0)

    for (int tb = 0; tb < NPTS; tb += TILE) {
        const int tlen = min(TILE, NPTS - tb);   // 960 or 512; both /8
        __syncthreads();
        for (int i = tid; i < tlen; i += KTHR) {
            const float* p = zb + (size_t)(tb + i) * 7;
            float x = p[0], y = p[1], w = p[2];
            tile4[i] = make_float4(x, y, w, 0.5f * (x * x + y * y + w * w));
        }
        __syncthreads();
        const int strip = tlen / NSPL;
        const int jb = s * strip;
        for (int j0 = jb; j0 < jb + strip; j0 += 8) {
#pragma unroll
            for (int u = 0; u < 8; u++) {
                float4 t4 = tile4[j0 + u];
                float scv = fmaf(-qz, t4.z, t4.w);
                scv = fmaf(-qy, t4.y, scv);
                scv = fmaf(-qx, t4.x, scv);
                if (scv < tau) {
                    cbuf[cnt][tid] = make_float2(scv, __int_as_float(tb + j0 + u));
                    cnt++;
                }
            }
            if (__any_sync(FULL, cnt >= CBUF - 8)) COMPACT();
        }
    }
    COMPACT();
#undef COMPACT

    __syncthreads();   // done with tile/cbuf; reuse raw for the 8-way merge
    float* md = (float*)raw;                         // 160*32*4 = 20480 B
    int*   mi = (int*)(raw + NSPL * KNN * QPB * 4);  // 20480 B
#pragma unroll
    for (int k = 0; k < KNN; k++) {
        md[(s * KNN + k) * QPB + lq] = bd[k];
        mi[(s * KNN + k) * QPB + lq] = bi[k];
    }
    __syncthreads();

    if (tid < QPB) {
        float fd[KNN]; int fi[KNN];
#pragma unroll
        for (int k = 0; k < KNN; k++) { fd[k] = 1e30f; fi[k] = -1; }
        for (int i = 0; i < NSPL * KNN; i++) {
            float d = md[i * QPB + tid];
            int  id = mi[i * QPB + tid];
            if (d < fd[KNN - 1]) {
#pragma unroll
                for (int k = KNN - 1; k > 0; --k) {
                    if (fd[k] > d) {
                        bool sh = fd[k - 1] > d;
                        fd[k] = sh ? fd[k - 1] : d;
                        fi[k] = sh ? fi[k - 1] : id;
                    }
                }
                if (fd[0] > d) { fd[0] = d; fi[0] = id; }
            }
        }
        int qq = blockIdx.x * QPB + tid;
        int* o = g_knn + ((size_t)b * NPTS + qq) * KNN;
#pragma unroll
        for (int k = 0; k < KNN; k++) o[k] = fi[k];
    }
}

// ---------------- kernel 3: edge MLP + softmax + aggregation + node MLP ----------------
// one warp per node. Per edge: lanes compute 4-unit partials, fold xor16,
// store one float4 (lanes 0-15). After the edge loop a single transpose-
// reduce gives lane e its edge's 4 outputs.
__global__ __launch_bounds__(256) void main_kernel(
    const float* __restrict__ z,
    const float* __restrict__ We1, const float* __restrict__ We2,
    const float* __restrict__ be2,
    const float* __restrict__ Wn1, const float* __restrict__ Wn2,
    const float* __restrict__ bn2,
    const float* __restrict__ alpha, const float* __restrict__ beta,
    float* __restrict__ out)
{
    __shared__ float4 part[8][KNN][17];

    const unsigned FULL = 0xffffffffu;
    const int wlocal = threadIdx.x >> 5;
    const int warp = (blockIdx.x * blockDim.x + threadIdx.x) >> 5;
    const int lane = threadIdx.x & 31;
    const int b = warp >> 13;
    const int n = warp & (NPTS - 1);

    const float* zb = z + (size_t)b * NPTS * 7;
    const float* zt = zb + (size_t)n * 7;
    const float ptx = zt[0], pty = zt[1], ptz = zt[2];
    const float vtx = zt[3], vty = zt[4], vtz = zt[5];
    const float mt  = zt[6];

    float relx = 0.f, rely = 0.f, relz = 0.f;
    float vsx = 0.f, vsy = 0.f, vsz = 0.f;
    float msrc = 0.f, r2 = 0.f, dvv = 0.f, dvr = 0.f, dtr = 0.f;
    if (lane < KNN) {
        int src = g_knn[(size_t)warp * KNN + lane];
        const float* zs = zb + (size_t)src * 7;
        float sx = zs[0], sy = zs[1], sz = zs[2];
        vsx = zs[3]; vsy = zs[4]; vsz = zs[5]; msrc = zs[6];
        relx = sx - ptx; rely = sy - pty; relz = sz - ptz;
        r2  = relx * relx + rely * rely + relz * relz;
        dvv = vsx * vtx + vsy * vty + vsz * vtz;
        dvr = vsx * relx + vsy * rely + vsz * relz;
        dtr = vtx * relx + vty * rely + vtz * relz;
    }

    float s1[4], s2[4], w72[4], w73[4], w74[4], w75[4], b1[4];
    float4 we2[4];
#pragma unroll
    for (int qq = 0; qq < 4; qq++) {
        int j = lane + 32 * qq;
        s1[qq]  = g_S1[j];
        s2[qq]  = g_S2[j];
        w72[qq] = We1[72 * 128 + j];
        w73[qq] = We1[73 * 128 + j];
        w74[qq] = We1[74 * 128 + j];
        w75[qq] = We1[75 * 128 + j];
        b1[qq]  = g_base1[b][j];
        we2[qq] = ((const float4*)We2)[j];
    }

#pragma unroll
    for (int e = 0; e < KNN; e++) {
        float em   = __shfl_sync(FULL, msrc, e);
        float er2  = __shfl_sync(FULL, r2,   e);
        float edvv = __shfl_sync(FULL, dvv,  e);
        float edvr = __shfl_sync(FULL, dvr,  e);
        float edtr = __shfl_sync(FULL, dtr,  e);
        float p0 = 0.f, p1 = 0.f, p2 = 0.f, p3 = 0.f;
#pragma unroll
        for (int qq = 0; qq < 4; qq++) {
            float h = b1[qq];
            h = fmaf(em,   s1[qq],  h);
            h = fmaf(mt,   s2[qq],  h);
            h = fmaf(er2,  w72[qq], h);
            h = fmaf(edvv, w73[qq], h);
            h = fmaf(edvr, w74[qq], h);
            h = fmaf(edtr, w75[qq], h);
            float g = gelu_fast(h);
            p0 = fmaf(g, we2[qq].x, p0);
            p1 = fmaf(g, we2[qq].y, p1);
            p2 = fmaf(g, we2[qq].z, p2);
            p3 = fmaf(g, we2[qq].w, p3);
        }
        p0 += __shfl_xor_sync(FULL, p0, 16);
        p1 += __shfl_xor_sync(FULL, p1, 16);
        p2 += __shfl_xor_sync(FULL, p2, 16);
        p3 += __shfl_xor_sync(FULL, p3, 16);
        if (lane < 16) part[wlocal][e][lane] = make_float4(p0, p1, p2, p3);
    }
    __syncwarp();

    float elog = -1e30f, esmsg = 0.f, ecrel = 0.f, ecvel = 0.f;
    if (lane < KNN) {
        float4 acc = part[wlocal][lane][0];
#pragma unroll
        for (int i = 1; i < 16; i++) {
            float4 p = part[wlocal][lane][i];
            acc.x += p.x; acc.y += p.y; acc.z += p.z; acc.w += p.w;
        }
        elog  = acc.x + be2[0];
        esmsg = acc.y + be2[1];
        ecrel = acc.z + be2[2];
        ecvel = acc.w + be2[3];
    }

    float lg = (lane < KNN) ? elog : -1e30f;
    float mx = lg;
#pragma unroll
    for (int off = 16; off > 0; off >>= 1)
        mx = fmaxf(mx, __shfl_xor_sync(FULL, mx, off));
    float a = (lane < KNN) ? __expf(lg - mx) : 0.f;
    float den = a;
#pragma unroll
    for (int off = 16; off > 0; off >>= 1)
        den += __shfl_xor_sync(FULL, den, off);
    float w = a / den;

    float vmx = w * (ecrel * relx + ecvel * vsx);
    float vmy = w * (ecrel * rely + ecvel * vsy);
    float vmz = w * (ecrel * relz + ecvel * vsz);
    float sg  = w * esmsg;
#pragma unroll
    for (int off = 16; off > 0; off >>= 1) {
        vmx += __shfl_xor_sync(FULL, vmx, off);
        vmy += __shfl_xor_sync(FULL, vmy, off);
        vmz += __shfl_xor_sync(FULL, vmz, off);
        sg  += __shfl_xor_sync(FULL, sg,  off);
    }

    float acc2 = 0.f;
#pragma unroll
    for (int qq = 0; qq < 2; qq++) {
        int j = lane + 32 * qq;
        float h = g_baseN[b][j];
        h = fmaf(mt, g_SN[j], h);
        h = fmaf(sg, Wn1[36 * 64 + j], h);
        acc2 = fmaf(gelu_fast(h), Wn2[j], acc2);
    }
#pragma unroll
    for (int off = 16; off > 0; off >>= 1)
        acc2 += __shfl_xor_sync(FULL, acc2, off);

    if (lane == 0) {
        float sout = acc2 + bn2[0];
        float al = alpha[0], be = beta[0];
        float* o = out + (size_t)warp * 7;
        o[0] = ptx + (ptx + al * vmx);
        o[1] = pty + (pty + al * vmy);
        o[2] = ptz + (ptz + al * vmz);
        o[3] = vtx + be * vmx;
        o[4] = vty + be * vmy;
        o[5] = vtz + be * vmz;
        o[6] = mt + sout;
    }
}

// ---------------- launch ----------------
extern "C" void kernel_launch(void* const* d_in, const int* in_sizes, int n_in,
                              void* d_out, int out_size)
{
    const float* z    = (const float*)d_in[0];
    const float* t    = (const float*)d_in[1];
    const float* cond = (const float*)d_in[2];
    const float* Wc1 = (const float*)d_in[4];
    const float* bc1 = (const float*)d_in[5];
    const float* Wc2 = (const float*)d_in[6];
    const float* bc2 = (const float*)d_in[7];
    const float* Wc3 = (const float*)d_in[8];
    const float* bc3 = (const float*)d_in[9];
    const float* We1 = (const float*)d_in[10];
    const float* be1 = (const float*)d_in[11];
    const float* We2 = (const float*)d_in[12];
    const float* be2 = (const float*)d_in[13];
    const float* Wn1 = (const float*)d_in[14];
    const float* bn1 = (const float*)d_in[15];
    const float* Wn2 = (const float*)d_in[16];
    const float* bn2 = (const float*)d_in[17];
    const float* alpha = (const float*)d_in[18];
    const float* beta  = (const float*)d_in[19];
    float* out = (float*)d_out;

    dim3 kg(NPTS / QPB, NB);
    knn_kernel<<<kg, KTHR>>>(z);

    setup_kernel<<<1, 256>>>(t, cond, Wc1, bc1, Wc2, bc2, Wc3, bc3,
                             We1, be1, Wn1, bn1);

    int total_warps = NB * NPTS;
    int blocks = total_warps / 8;
    main_kernel<<<blocks, 256>>>(z, We1, We2, be2, Wn1, Wn2, bn2,
                                 alpha, beta, out);
}

// round 12
// speedup vs baseline: 7.5334x; 1.2092x over previous
#include <cuda_runtime.h>
#include <math.h>

#define NB    2
#define NPTS  8192
#define KNN   20
#define GDIM  16
#define G3    (GDIM*GDIM*GDIM)
#define CHUNK 64
#define NCH   (NPTS/CHUNK)    // 128
#define NSPL  4
#define KTHR  128
#define CBUF  16

// ---------------- device scratch (no allocation allowed) ----------------
__device__ int    g_knn[NB * NPTS * KNN];
__device__ float  g_S1[128], g_S2[128], g_SN[64];
__device__ float  g_base1[NB][128];
__device__ float  g_baseN[NB][64];
// sorted-point structures
__device__ float4 g_pts4[NB * NPTS];     // cell-sorted (x,y,z, 0.5*|p|^2)
__device__ int    g_ids [NB * NPTS];
__device__ int    g_cellstart[NB * (G3 + 1)];
__device__ int    g_cnt[NB * G3];
__device__ float  g_lo[NB][3];
__device__ float  g_invs[NB][3];
__device__ float4 g_chlo[NB][NCH];
__device__ float4 g_chhi[NB][NCH];

__device__ __forceinline__ float gelu_f(float x) {
    float y = 0.7978845608028654f * (x + 0.044715f * x * x * x);
    float e = __expf(2.0f * y);
    float th = 1.0f - 2.0f / (e + 1.0f);
    return 0.5f * x * (1.0f + th);
}

__device__ __forceinline__ float gelu_fast(float x) {
    float y = 0.7978845608028654f * fmaf(0.044715f * x * x, x, x);
    float t;
    asm("tanh.approx.f32 %0, %1;" : "=f"(t) : "f"(y));
    return 0.5f * x * (1.0f + t);
}

__device__ __forceinline__ int cell_of(float v, float lo, float inv) {
    int i = (int)((v - lo) * inv);
    return i < 0 ? 0 : (i > GDIM - 1 ? GDIM - 1 : i);
}

// ---------------- builder 1: zero counts + bbox ----------------
__global__ __launch_bounds__(256) void grid_bbox_kernel(const float* __restrict__ z)
{
    const int b   = blockIdx.x;
    const int tid = threadIdx.x;
    const unsigned FULL = 0xffffffffu;

    for (int i = tid; i < G3; i += 256) g_cnt[b * G3 + i] = 0;

    float lx = 1e30f, ly = 1e30f, lz = 1e30f;
    float hx = -1e30f, hy = -1e30f, hz = -1e30f;
    const float* zb = z + (size_t)b * NPTS * 7;
    for (int n = tid; n < NPTS; n += 256) {
        const float* p = zb + (size_t)n * 7;
        float x = p[0], y = p[1], w = p[2];
        lx = fminf(lx, x); hx = fmaxf(hx, x);
        ly = fminf(ly, y); hy = fmaxf(hy, y);
        lz = fminf(lz, w); hz = fmaxf(hz, w);
    }
#pragma unroll
    for (int off = 16; off > 0; off >>= 1) {
        lx = fminf(lx, __shfl_xor_sync(FULL, lx, off));
        ly = fminf(ly, __shfl_xor_sync(FULL, ly, off));
        lz = fminf(lz, __shfl_xor_sync(FULL, lz, off));
        hx = fmaxf(hx, __shfl_xor_sync(FULL, hx, off));
        hy = fmaxf(hy, __shfl_xor_sync(FULL, hy, off));
        hz = fmaxf(hz, __shfl_xor_sync(FULL, hz, off));
    }
    __shared__ float slo[8][3], shi[8][3];
    const int warp = tid >> 5;
    if ((tid & 31) == 0) {
        slo[warp][0] = lx; slo[warp][1] = ly; slo[warp][2] = lz;
        shi[warp][0] = hx; shi[warp][1] = hy; shi[warp][2] = hz;
    }
    __syncthreads();
    if (tid == 0) {
        for (int w2 = 1; w2 < 8; w2++) {
            slo[0][0] = fminf(slo[0][0], slo[w2][0]);
            slo[0][1] = fminf(slo[0][1], slo[w2][1]);
            slo[0][2] = fminf(slo[0][2], slo[w2][2]);
            shi[0][0] = fmaxf(shi[0][0], shi[w2][0]);
            shi[0][1] = fmaxf(shi[0][1], shi[w2][1]);
            shi[0][2] = fmaxf(shi[0][2], shi[w2][2]);
        }
        for (int d = 0; d < 3; d++) {
            float span = fmaxf(shi[0][d] - slo[0][d], 1e-5f);
            g_lo[b][d]   = slo[0][d];
            g_invs[b][d] = (float)GDIM / span;
        }
    }
}

// ---------------- builder 2: count ----------------
__global__ __launch_bounds__(256) void grid_count_kernel(const float* __restrict__ z)
{
    int i = blockIdx.x * 256 + threadIdx.x;
    int b = i >> 13;
    int n = i & (NPTS - 1);
    const float* p = z + ((size_t)b * NPTS + n) * 7;
    int cx = cell_of(p[0], g_lo[b][0], g_invs[b][0]);
    int cy = cell_of(p[1], g_lo[b][1], g_invs[b][1]);
    int cz = cell_of(p[2], g_lo[b][2], g_invs[b][2]);
    atomicAdd(&g_cnt[b * G3 + (cx * GDIM + cy) * GDIM + cz], 1);
}

// ---------------- builder 3: exclusive scan ----------------
__global__ __launch_bounds__(1024) void grid_scan_kernel()
{
    __shared__ int sm[1024];
    const int b = blockIdx.x;
    const int t = threadIdx.x;
    const int base = t * (G3 / 1024);

    int sum = 0;
#pragma unroll
    for (int k = 0; k < G3 / 1024; k++) sum += g_cnt[b * G3 + base + k];
    sm[t] = sum;
    __syncthreads();
    for (int off = 1; off < 1024; off <<= 1) {
        int v = (t >= off) ? sm[t - off] : 0;
        __syncthreads();
        sm[t] += v;
        __syncthreads();
    }
    int running = sm[t] - sum;
#pragma unroll
    for (int k = 0; k < G3 / 1024; k++) {
        int c = base + k;
        int cc = g_cnt[b * G3 + c];
        g_cellstart[b * (G3 + 1) + c] = running;
        g_cnt[b * G3 + c] = running;
        running += cc;
    }
    if (t == 1023) g_cellstart[b * (G3 + 1) + G3] = running;
}

// ---------------- builder 4: scatter into cell-sorted order ----------------
__global__ __launch_bounds__(256) void grid_scatter_kernel(const float* __restrict__ z)
{
    int i = blockIdx.x * 256 + threadIdx.x;
    int b = i >> 13;
    int n = i & (NPTS - 1);
    const float* p = z + ((size_t)b * NPTS + n) * 7;
    float x = p[0], y = p[1], w = p[2];
    int cx = cell_of(x, g_lo[b][0], g_invs[b][0]);
    int cy = cell_of(y, g_lo[b][1], g_invs[b][1]);
    int cz = cell_of(w, g_lo[b][2], g_invs[b][2]);
    int pos = atomicAdd(&g_cnt[b * G3 + (cx * GDIM + cy) * GDIM + cz], 1);
    g_pts4[b * NPTS + pos] = make_float4(x, y, w, 0.5f * (x * x + y * y + w * w));
    g_ids [b * NPTS + pos] = n;
}

// ---------------- builder 5: 64-point chunk bboxes ----------------
__global__ __launch_bounds__(256) void chunk_bbox_kernel()
{
    const unsigned FULL = 0xffffffffu;
    const int b    = blockIdx.x;
    const int warp = threadIdx.x >> 5;
    const int lane = threadIdx.x & 31;
    const float4* pts = g_pts4 + (size_t)b * NPTS;

    for (int ch = warp; ch < NCH; ch += 8) {
        float4 a = pts[ch * CHUNK + lane];
        float4 c = pts[ch * CHUNK + 32 + lane];
        float lx = fminf(a.x, c.x), hx = fmaxf(a.x, c.x);
        float ly = fminf(a.y, c.y), hy = fmaxf(a.y, c.y);
        float lz = fminf(a.z, c.z), hz = fmaxf(a.z, c.z);
#pragma unroll
        for (int off = 16; off > 0; off >>= 1) {
            lx = fminf(lx, __shfl_xor_sync(FULL, lx, off));
            ly = fminf(ly, __shfl_xor_sync(FULL, ly, off));
            lz = fminf(lz, __shfl_xor_sync(FULL, lz, off));
            hx = fmaxf(hx, __shfl_xor_sync(FULL, hx, off));
            hy = fmaxf(hy, __shfl_xor_sync(FULL, hy, off));
            hz = fmaxf(hz, __shfl_xor_sync(FULL, hz, off));
        }
        if (lane == 0) {
            g_chlo[b][ch] = make_float4(lx, ly, lz, 0.f);
            g_chhi[b][ch] = make_float4(hx, hy, hz, 0.f);
        }
    }
}

// ---------------- kNN query: R5 lockstep scan + chunk-bbox pruning ----------------
// 128 threads = 32 sorted-adjacent queries (lane) x 4 split warps (chunks
// dealt round-robin). Pass 1 scans the home +-1 chunks (seeds tau); pass 2
// walks all other chunks with a per-lane box-distance test + warp ballot
// skip. tau only shrinks, so skipping is exact. score = 0.5|p|^2 - q.p;
// d^2 threshold = 2*tau + |q|^2.
__global__ __launch_bounds__(KTHR) void knn_query_kernel()
{
    __shared__ __align__(16) unsigned char raw[20480];
    __shared__ float tau_sh[32];
    float2 (*cbuf)[KTHR] = (float2 (*)[KTHR])raw;          // 16 KB

    const unsigned FULL = 0xffffffffu;
    const int tid  = threadIdx.x;
    const int lq   = tid & 31;
    const int s    = tid >> 5;
    const int b    = blockIdx.y;
    const int sbase = blockIdx.x * 32;
    const int slot  = sbase + lq;

    const float4* pts = g_pts4 + (size_t)b * NPTS;

    float4 q4 = pts[slot];
    const float qx = q4.x, qy = q4.y, qz = q4.z;
    const float qr2 = 2.0f * q4.w;

    if (tid < 32) tau_sh[tid] = 1e30f;
    __syncthreads();

    float bd[KNN];
    int   bi[KNN];
#pragma unroll
    for (int k = 0; k < KNN; k++) { bd[k] = 1e30f; bi[k] = -1; }

    int   cnt = 0;
    float tau = 1e30f;

#define COMPACT() do {                                                        \
    for (int i = 0; i < cnt; i++) {                                           \
        float2 c = cbuf[i][tid];                                              \
        float d = c.x;                                                        \
        int  id = __float_as_int(c.y);                                        \
        if (d < bd[KNN - 1] && id != slot) {                                  \
            _Pragma("unroll")                                                 \
            for (int k = KNN - 1; k > 0; --k) {                               \
                if (bd[k] > d) {                                              \
                    bool sh = bd[k - 1] > d;                                  \
                    bd[k] = sh ? bd[k - 1] : d;                               \
                    bi[k] = sh ? bi[k - 1] : id;                              \
                }                                                             \
            }                                                                 \
            if (bd[0] > d) { bd[0] = d; bi[0] = id; }                         \
        }                                                                     \
    }                                                                         \
    cnt = 0;                                                                  \
    tau_sh[lq] = fminf(tau_sh[lq], bd[KNN - 1]);                              \
    tau = fminf(bd[KNN - 1], tau_sh[lq]);                                     \
} while (0)

#define SCAN_CHUNK(c) do {                                                    \
    int jb = (c) * CHUNK;                                                     \
    for (int j0 = jb; j0 < jb + CHUNK; j0 += 8) {                             \
        _Pragma("unroll")                                                     \
        for (int u = 0; u < 8; u++) {                                         \
            int j = j0 + u;                                                   \
            float4 t4 = pts[j];                                               \
            float sv = fmaf(-qz, t4.z, t4.w);                                 \
            sv = fmaf(-qy, t4.y, sv);                                         \
            sv = fmaf(-qx, t4.x, sv);                                         \
            if (sv < tau) {                                                   \
                cbuf[cnt][tid] = make_float2(sv, __int_as_float(j));          \
                cnt++;                                                        \
            }                                                                 \
        }                                                                     \
        if (__any_sync(FULL, cnt >= CBUF - 8)) COMPACT();                     \
    }                                                                         \
} while (0)

    // home range (warp-uniform)
    const int h0 = max(sbase / CHUNK - 1, 0);
    const int h1 = min((sbase + 31) / CHUNK + 1, NCH - 1);

    // pass 1: seed tau from home chunks
    for (int c = h0 + s; c <= h1; c += NSPL) SCAN_CHUNK(c);
    COMPACT();
    __syncthreads();                 // seeds visible across split warps
    tau = fminf(bd[KNN - 1], tau_sh[lq]);

    // pass 2: pruned walk over all other chunks
    for (int c = s; c < NCH; c += NSPL) {
        if (c >= h0 && c <= h1) continue;
        float4 lo = g_chlo[b][c];
        float4 hi = g_chhi[b][c];
        float dx = fmaxf(fmaxf(lo.x - qx, qx - hi.x), 0.f);
        float dy = fmaxf(fmaxf(lo.y - qy, qy - hi.y), 0.f);
        float dz = fmaxf(fmaxf(lo.z - qz, qz - hi.z), 0.f);
        float d2box = fmaf(dx, dx, fmaf(dy, dy, dz * dz));
        float thr = fmaf(2.0f, tau, qr2) * 1.0002f;
        if (__any_sync(FULL, d2box < thr)) SCAN_CHUNK(c);
    }
    COMPACT();
#undef SCAN_CHUNK
#undef COMPACT

    __syncthreads();   // reuse raw for the 4-way merge
    float* md = (float*)raw;                         // 80*32*4 = 10240 B
    int*   mi = (int*)(raw + NSPL * KNN * 32 * 4);   // 10240 B
#pragma unroll
    for (int k = 0; k < KNN; k++) {
        md[(s * KNN + k) * 32 + lq] = bd[k];
        mi[(s * KNN + k) * 32 + lq] = bi[k];
    }
    __syncthreads();

    if (tid < 32) {
        float fd[KNN]; int fi[KNN];
#pragma unroll
        for (int k = 0; k < KNN; k++) { fd[k] = 1e30f; fi[k] = -1; }
        for (int i = 0; i < NSPL * KNN; i++) {
            float d = md[i * 32 + tid];
            int  id = mi[i * 32 + tid];
            if (d < fd[KNN - 1]) {
#pragma unroll
                for (int k = KNN - 1; k > 0; --k) {
                    if (fd[k] > d) {
                        bool sh = fd[k - 1] > d;
                        fd[k] = sh ? fd[k - 1] : d;
                        fi[k] = sh ? fi[k - 1] : id;
                    }
                }
                if (fd[0] > d) { fd[0] = d; fi[0] = id; }
            }
        }
        const int* ids = g_ids + (size_t)b * NPTS;
        int myslot = sbase + tid;
        int* o = g_knn + ((size_t)b * NPTS + ids[myslot]) * KNN;
#pragma unroll
        for (int k = 0; k < KNN; k++) o[k] = ids[fi[k]];
    }
}

// ---------------- setup: cond MLP + folded per-batch vectors ----------------
__global__ __launch_bounds__(256) void setup_kernel(
    const float* __restrict__ t, const float* __restrict__ conditioning,
    const float* __restrict__ Wc1, const float* __restrict__ bc1,
    const float* __restrict__ Wc2, const float* __restrict__ bc2,
    const float* __restrict__ Wc3, const float* __restrict__ bc3,
    const float* __restrict__ We1, const float* __restrict__ be1,
    const float* __restrict__ Wn1, const float* __restrict__ bn1)
{
    const unsigned FULL = 0xffffffffu;
    const int tid  = threadIdx.x;
    const int lane = tid & 31;
    const int warp = tid >> 5;

    if (tid < 128) {
        float s1 = 0.f, s2 = 0.f;
#pragma unroll
        for (int c = 0; c < 36; c++) {
            s1 += We1[c * 128 + tid];
            s2 += We1[(36 + c) * 128 + tid];
        }
        g_S1[tid] = s1;
        g_S2[tid] = s2;
    }
    if (tid < 64) {
        float sn = 0.f;
#pragma unroll
        for (int c = 0; c < 36; c++) sn += Wn1[c * 64 + tid];
        g_SN[tid] = sn;
    }

    __shared__ float sc[36], h1[144], h2[144], cv[40];

    for (int b = 0; b < NB; b++) {
        if (tid < 36) {
            float v;
            if (tid < 16) {
                float f = expf(-logf(10000.0f) * (float)tid / 15.0f);
                v = sinf(t[b] * f);
            } else if (tid < 32) {
                int i = tid - 16;
                float f = expf(-logf(10000.0f) * (float)i / 15.0f);
                v = cosf(t[b] * f);
            } else {
                v = conditioning[b * 4 + (tid - 32)];
            }
            sc[tid] = v;
        }
        __syncthreads();
        if (tid < 144) {
            float a = bc1[tid];
#pragma unroll
            for (int c = 0; c < 36; c++) a = fmaf(sc[c], Wc1[c * 144 + tid], a);
            h1[tid] = gelu_f(a);
        }
        __syncthreads();
        for (int o = 0; o < 18; o++) {
            int j = warp + 8 * o;
            float a = 0.f;
#pragma unroll
            for (int r = 0; r < 5; r++) {
                int c = lane + 32 * r;
                if (c < 144) a = fmaf(h1[c], Wc2[c * 144 + j], a);
            }
#pragma unroll
            for (int off = 16; off > 0; off >>= 1)
                a += __shfl_xor_sync(FULL, a, off);
            if (lane == 0) h2[j] = gelu_f(a + bc2[j]);
        }
        __syncthreads();
        for (int o = 0; o < 5; o++) {
            int j = warp + 8 * o;
            if (j < 36) {
                float a = 0.f;
#pragma unroll
                for (int r = 0; r < 5; r++) {
                    int c = lane + 32 * r;
                    if (c < 144) a = fmaf(h2[c], Wc3[c * 36 + j], a);
                }
#pragma unroll
                for (int off = 16; off > 0; off >>= 1)
                    a += __shfl_xor_sync(FULL, a, off);
                if (lane == 0) cv[j] = a + bc3[j];
            }
        }
        __syncthreads();
        if (tid < 128) {
            float a = be1[tid];
#pragma unroll
            for (int c = 0; c < 36; c++)
                a = fmaf(cv[c], We1[c * 128 + tid] + We1[(36 + c) * 128 + tid], a);
            g_base1[b][tid] = a;
        }
        if (tid < 64) {
            float a = bn1[tid];
#pragma unroll
            for (int c = 0; c < 36; c++) a = fmaf(cv[c], Wn1[c * 64 + tid], a);
            g_baseN[b][tid] = a;
        }
        __syncthreads();
    }
}

// ---------------- main: edge MLP + softmax + aggregation + node MLP ----------------
__global__ __launch_bounds__(256) void main_kernel(
    const float* __restrict__ z,
    const float* __restrict__ We1, const float* __restrict__ We2,
    const float* __restrict__ be2,
    const float* __restrict__ Wn1, const float* __restrict__ Wn2,
    const float* __restrict__ bn2,
    const float* __restrict__ alpha, const float* __restrict__ beta,
    float* __restrict__ out)
{
    __shared__ float4 part[8][KNN][17];

    const unsigned FULL = 0xffffffffu;
    const int wlocal = threadIdx.x >> 5;
    const int warp = (blockIdx.x * blockDim.x + threadIdx.x) >> 5;
    const int lane = threadIdx.x & 31;
    const int b = warp >> 13;
    const int n = warp & (NPTS - 1);

    const float* zb = z + (size_t)b * NPTS * 7;
    const float* zt = zb + (size_t)n * 7;
    const float ptx = zt[0], pty = zt[1], ptz = zt[2];
    const float vtx = zt[3], vty = zt[4], vtz = zt[5];
    const float mt  = zt[6];

    float relx = 0.f, rely = 0.f, relz = 0.f;
    float vsx = 0.f, vsy = 0.f, vsz = 0.f;
    float msrc = 0.f, r2 = 0.f, dvv = 0.f, dvr = 0.f, dtr = 0.f;
    if (lane < KNN) {
        int src = g_knn[(size_t)warp * KNN + lane];
        const float* zs = zb + (size_t)src * 7;
        float sx = zs[0], sy = zs[1], sz = zs[2];
        vsx = zs[3]; vsy = zs[4]; vsz = zs[5]; msrc = zs[6];
        relx = sx - ptx; rely = sy - pty; relz = sz - ptz;
        r2  = relx * relx + rely * rely + relz * relz;
        dvv = vsx * vtx + vsy * vty + vsz * vtz;
        dvr = vsx * relx + vsy * rely + vsz * relz;
        dtr = vtx * relx + vty * rely + vtz * relz;
    }

    float s1[4], s2[4], w72[4], w73[4], w74[4], w75[4], b1[4];
    float4 we2[4];
#pragma unroll
    for (int qq = 0; qq < 4; qq++) {
        int j = lane + 32 * qq;
        s1[qq]  = g_S1[j];
        s2[qq]  = g_S2[j];
        w72[qq] = We1[72 * 128 + j];
        w73[qq] = We1[73 * 128 + j];
        w74[qq] = We1[74 * 128 + j];
        w75[qq] = We1[75 * 128 + j];
        b1[qq]  = g_base1[b][j];
        we2[qq] = ((const float4*)We2)[j];
    }

#pragma unroll
    for (int e = 0; e < KNN; e++) {
        float em   = __shfl_sync(FULL, msrc, e);
        float er2  = __shfl_sync(FULL, r2,   e);
        float edvv = __shfl_sync(FULL, dvv,  e);
        float edvr = __shfl_sync(FULL, dvr,  e);
        float edtr = __shfl_sync(FULL, dtr,  e);
        float p0 = 0.f, p1 = 0.f, p2 = 0.f, p3 = 0.f;
#pragma unroll
        for (int qq = 0; qq < 4; qq++) {
            float h = b1[qq];
            h = fmaf(em,   s1[qq],  h);
            h = fmaf(mt,   s2[qq],  h);
            h = fmaf(er2,  w72[qq], h);
            h = fmaf(edvv, w73[qq], h);
            h = fmaf(edvr, w74[qq], h);
            h = fmaf(edtr, w75[qq], h);
            float g = gelu_fast(h);
            p0 = fmaf(g, we2[qq].x, p0);
            p1 = fmaf(g, we2[qq].y, p1);
            p2 = fmaf(g, we2[qq].z, p2);
            p3 = fmaf(g, we2[qq].w, p3);
        }
        p0 += __shfl_xor_sync(FULL, p0, 16);
        p1 += __shfl_xor_sync(FULL, p1, 16);
        p2 += __shfl_xor_sync(FULL, p2, 16);
        p3 += __shfl_xor_sync(FULL, p3, 16);
        if (lane < 16) part[wlocal][e][lane] = make_float4(p0, p1, p2, p3);
    }
    __syncwarp();

    float elog = -1e30f, esmsg = 0.f, ecrel = 0.f, ecvel = 0.f;
    if (lane < KNN) {
        float4 acc = part[wlocal][lane][0];
#pragma unroll
        for (int i = 1; i < 16; i++) {
            float4 p = part[wlocal][lane][i];
            acc.x += p.x; acc.y += p.y; acc.z += p.z; acc.w += p.w;
        }
        elog  = acc.x + be2[0];
        esmsg = acc.y + be2[1];
        ecrel = acc.z + be2[2];
        ecvel = acc.w + be2[3];
    }

    float lg = (lane < KNN) ? elog : -1e30f;
    float mx = lg;
#pragma unroll
    for (int off = 16; off > 0; off >>= 1)
        mx = fmaxf(mx, __shfl_xor_sync(FULL, mx, off));
    float a = (lane < KNN) ? __expf(lg - mx) : 0.f;
    float den = a;
#pragma unroll
    for (int off = 16; off > 0; off >>= 1)
        den += __shfl_xor_sync(FULL, den, off);
    float w = a / den;

    float vmx = w * (ecrel * relx + ecvel * vsx);
    float vmy = w * (ecrel * rely + ecvel * vsy);
    float vmz = w * (ecrel * relz + ecvel * vsz);
    float sg  = w * esmsg;
#pragma unroll
    for (int off = 16; off > 0; off >>= 1) {
        vmx += __shfl_xor_sync(FULL, vmx, off);
        vmy += __shfl_xor_sync(FULL, vmy, off);
        vmz += __shfl_xor_sync(FULL, vmz, off);
        sg  += __shfl_xor_sync(FULL, sg,  off);
    }

    float acc2 = 0.f;
#pragma unroll
    for (int qq = 0; qq < 2; qq++) {
        int j = lane + 32 * qq;
        float h = g_baseN[b][j];
        h = fmaf(mt, g_SN[j], h);
        h = fmaf(sg, Wn1[36 * 64 + j], h);
        acc2 = fmaf(gelu_fast(h), Wn2[j], acc2);
    }
#pragma unroll
    for (int off = 16; off > 0; off >>= 1)
        acc2 += __shfl_xor_sync(FULL, acc2, off);

    if (lane == 0) {
        float sout = acc2 + bn2[0];
        float al = alpha[0], be = beta[0];
        float* o = out + (size_t)warp * 7;
        o[0] = ptx + (ptx + al * vmx);
        o[1] = pty + (pty + al * vmy);
        o[2] = ptz + (ptz + al * vmz);
        o[3] = vtx + be * vmx;
        o[4] = vty + be * vmy;
        o[5] = vtz + be * vmz;
        o[6] = mt + sout;
    }
}

// ---------------- launch ----------------
extern "C" void kernel_launch(void* const* d_in, const int* in_sizes, int n_in,
                              void* d_out, int out_size)
{
    const float* z    = (const float*)d_in[0];
    const float* t    = (const float*)d_in[1];
    const float* cond = (const float*)d_in[2];
    const float* Wc1 = (const float*)d_in[4];
    const float* bc1 = (const float*)d_in[5];
    const float* Wc2 = (const float*)d_in[6];
    const float* bc2 = (const float*)d_in[7];
    const float* Wc3 = (const float*)d_in[8];
    const float* bc3 = (const float*)d_in[9];
    const float* We1 = (const float*)d_in[10];
    const float* be1 = (const float*)d_in[11];
    const float* We2 = (const float*)d_in[12];
    const float* be2 = (const float*)d_in[13];
    const float* Wn1 = (const float*)d_in[14];
    const float* bn1 = (const float*)d_in[15];
    const float* Wn2 = (const float*)d_in[16];
    const float* bn2 = (const float*)d_in[17];
    const float* alpha = (const float*)d_in[18];
    const float* beta  = (const float*)d_in[19];
    float* out = (float*)d_out;

    grid_bbox_kernel<<<NB, 256>>>(z);
    grid_count_kernel<<<NB * NPTS / 256, 256>>>(z);
    grid_scan_kernel<<<NB, 1024>>>();
    grid_scatter_kernel<<<NB * NPTS / 256, 256>>>(z);
    chunk_bbox_kernel<<<NB, 256>>>();

    dim3 qg(NPTS / 32, NB);
    knn_query_kernel<<<qg, KTHR>>>();

    setup_kernel<<<1, 256>>>(t, cond, Wc1, bc1, Wc2, bc2, Wc3, bc3,
                             We1, be1, Wn1, bn1);

    int total_warps = NB * NPTS;
    int blocks = total_warps / 8;
    main_kernel<<<blocks, 256>>>(z, We1, We2, be2, Wn1, Wn2, bn2,
                                 alpha, beta, out);
}

// round 13
// speedup vs baseline: 8.2068x; 1.0894x over previous
#include <cuda_runtime.h>
#include <math.h>

#define NB    2
#define NPTS  8192
#define KNN   20
#define GDIM  16
#define G3    (GDIM*GDIM*GDIM)
#define CHUNK 64
#define NCH   (NPTS/CHUNK)    // 128
#define NSPL  4
#define KTHR  128
#define CBUF  16

// ---------------- device scratch (no allocation allowed) ----------------
__device__ int    g_knn[NB * NPTS * KNN];
__device__ float  g_S1[128], g_S2[128], g_SN[64];
__device__ float  g_base1[NB][128];
__device__ float  g_baseN[NB][64];
// sorted-point structures
__device__ float4 g_pts4[NB * NPTS];     // Morton-cell-sorted (x,y,z, 0.5*|p|^2)
__device__ int    g_ids [NB * NPTS];
__device__ int    g_cellstart[NB * (G3 + 1)];
__device__ int    g_cnt[NB * G3];
__device__ float  g_lo[NB][3];
__device__ float  g_invs[NB][3];
__device__ float4 g_chlo[NB][NCH];
__device__ float4 g_chhi[NB][NCH];

__device__ __forceinline__ float gelu_f(float x) {
    float y = 0.7978845608028654f * (x + 0.044715f * x * x * x);
    float e = __expf(2.0f * y);
    float th = 1.0f - 2.0f / (e + 1.0f);
    return 0.5f * x * (1.0f + th);
}

__device__ __forceinline__ float gelu_fast(float x) {
    float y = 0.7978845608028654f * fmaf(0.044715f * x * x, x, x);
    float t;
    asm("tanh.approx.f32 %0, %1;" : "=f"(t) : "f"(y));
    return 0.5f * x * (1.0f + t);
}

__device__ __forceinline__ int cell_of(float v, float lo, float inv) {
    int i = (int)((v - lo) * inv);
    return i < 0 ? 0 : (i > GDIM - 1 ? GDIM - 1 : i);
}

// 4-bit-per-axis Morton interleave: compact chunks => tight bboxes
__device__ __forceinline__ int morton3(int x, int y, int z) {
    int m = 0;
#pragma unroll
    for (int i = 0; i < 4; i++) {
        m |= (((x >> i) & 1) << (3 * i + 2))
           | (((y >> i) & 1) << (3 * i + 1))
           | (((z >> i) & 1) << (3 * i));
    }
    return m;
}

// ---------------- builder 1: zero counts + bbox ----------------
__global__ __launch_bounds__(256) void grid_bbox_kernel(const float* __restrict__ z)
{
    const int b   = blockIdx.x;
    const int tid = threadIdx.x;
    const unsigned FULL = 0xffffffffu;

    for (int i = tid; i < G3; i += 256) g_cnt[b * G3 + i] = 0;

    float lx = 1e30f, ly = 1e30f, lz = 1e30f;
    float hx = -1e30f, hy = -1e30f, hz = -1e30f;
    const float* zb = z + (size_t)b * NPTS * 7;
    for (int n = tid; n < NPTS; n += 256) {
        const float* p = zb + (size_t)n * 7;
        float x = p[0], y = p[1], w = p[2];
        lx = fminf(lx, x); hx = fmaxf(hx, x);
        ly = fminf(ly, y); hy = fmaxf(hy, y);
        lz = fminf(lz, w); hz = fmaxf(hz, w);
    }
#pragma unroll
    for (int off = 16; off > 0; off >>= 1) {
        lx = fminf(lx, __shfl_xor_sync(FULL, lx, off));
        ly = fminf(ly, __shfl_xor_sync(FULL, ly, off));
        lz = fminf(lz, __shfl_xor_sync(FULL, lz, off));
        hx = fmaxf(hx, __shfl_xor_sync(FULL, hx, off));
        hy = fmaxf(hy, __shfl_xor_sync(FULL, hy, off));
        hz = fmaxf(hz, __shfl_xor_sync(FULL, hz, off));
    }
    __shared__ float slo[8][3], shi[8][3];
    const int warp = tid >> 5;
    if ((tid & 31) == 0) {
        slo[warp][0] = lx; slo[warp][1] = ly; slo[warp][2] = lz;
        shi[warp][0] = hx; shi[warp][1] = hy; shi[warp][2] = hz;
    }
    __syncthreads();
    if (tid == 0) {
        for (int w2 = 1; w2 < 8; w2++) {
            slo[0][0] = fminf(slo[0][0], slo[w2][0]);
            slo[0][1] = fminf(slo[0][1], slo[w2][1]);
            slo[0][2] = fminf(slo[0][2], slo[w2][2]);
            shi[0][0] = fmaxf(shi[0][0], shi[w2][0]);
            shi[0][1] = fmaxf(shi[0][1], shi[w2][1]);
            shi[0][2] = fmaxf(shi[0][2], shi[w2][2]);
        }
        for (int d = 0; d < 3; d++) {
            float span = fmaxf(shi[0][d] - slo[0][d], 1e-5f);
            g_lo[b][d]   = slo[0][d];
            g_invs[b][d] = (float)GDIM / span;
        }
    }
}

// ---------------- builder 2: count (Morton cell index) ----------------
__global__ __launch_bounds__(256) void grid_count_kernel(const float* __restrict__ z)
{
    int i = blockIdx.x * 256 + threadIdx.x;
    int b = i >> 13;
    int n = i & (NPTS - 1);
    const float* p = z + ((size_t)b * NPTS + n) * 7;
    int cx = cell_of(p[0], g_lo[b][0], g_invs[b][0]);
    int cy = cell_of(p[1], g_lo[b][1], g_invs[b][1]);
    int cz = cell_of(p[2], g_lo[b][2], g_invs[b][2]);
    atomicAdd(&g_cnt[b * G3 + morton3(cx, cy, cz)], 1);
}

// ---------------- builder 3: exclusive scan ----------------
__global__ __launch_bounds__(1024) void grid_scan_kernel()
{
    __shared__ int sm[1024];
    const int b = blockIdx.x;
    const int t = threadIdx.x;
    const int base = t * (G3 / 1024);

    int sum = 0;
#pragma unroll
    for (int k = 0; k < G3 / 1024; k++) sum += g_cnt[b * G3 + base + k];
    sm[t] = sum;
    __syncthreads();
    for (int off = 1; off < 1024; off <<= 1) {
        int v = (t >= off) ? sm[t - off] : 0;
        __syncthreads();
        sm[t] += v;
        __syncthreads();
    }
    int running = sm[t] - sum;
#pragma unroll
    for (int k = 0; k < G3 / 1024; k++) {
        int c = base + k;
        int cc = g_cnt[b * G3 + c];
        g_cellstart[b * (G3 + 1) + c] = running;
        g_cnt[b * G3 + c] = running;
        running += cc;
    }
    if (t == 1023) g_cellstart[b * (G3 + 1) + G3] = running;
}

// ---------------- builder 4: scatter into Morton-sorted order ----------------
__global__ __launch_bounds__(256) void grid_scatter_kernel(const float* __restrict__ z)
{
    int i = blockIdx.x * 256 + threadIdx.x;
    int b = i >> 13;
    int n = i & (NPTS - 1);
    const float* p = z + ((size_t)b * NPTS + n) * 7;
    float x = p[0], y = p[1], w = p[2];
    int cx = cell_of(x, g_lo[b][0], g_invs[b][0]);
    int cy = cell_of(y, g_lo[b][1], g_invs[b][1]);
    int cz = cell_of(w, g_lo[b][2], g_invs[b][2]);
    int pos = atomicAdd(&g_cnt[b * G3 + morton3(cx, cy, cz)], 1);
    g_pts4[b * NPTS + pos] = make_float4(x, y, w, 0.5f * (x * x + y * y + w * w));
    g_ids [b * NPTS + pos] = n;
}

// ---------------- builder 5: 64-point chunk bboxes ----------------
__global__ __launch_bounds__(256) void chunk_bbox_kernel()
{
    const unsigned FULL = 0xffffffffu;
    const int b    = blockIdx.x;
    const int warp = threadIdx.x >> 5;
    const int lane = threadIdx.x & 31;
    const float4* pts = g_pts4 + (size_t)b * NPTS;

    for (int ch = warp; ch < NCH; ch += 8) {
        float4 a = pts[ch * CHUNK + lane];
        float4 c = pts[ch * CHUNK + 32 + lane];
        float lx = fminf(a.x, c.x), hx = fmaxf(a.x, c.x);
        float ly = fminf(a.y, c.y), hy = fmaxf(a.y, c.y);
        float lz = fminf(a.z, c.z), hz = fmaxf(a.z, c.z);
#pragma unroll
        for (int off = 16; off > 0; off >>= 1) {
            lx = fminf(lx, __shfl_xor_sync(FULL, lx, off));
            ly = fminf(ly, __shfl_xor_sync(FULL, ly, off));
            lz = fminf(lz, __shfl_xor_sync(FULL, lz, off));
            hx = fmaxf(hx, __shfl_xor_sync(FULL, hx, off));
            hy = fmaxf(hy, __shfl_xor_sync(FULL, hy, off));
            hz = fmaxf(hz, __shfl_xor_sync(FULL, hz, off));
        }
        if (lane == 0) {
            g_chlo[b][ch] = make_float4(lx, ly, lz, 0.f);
            g_chhi[b][ch] = make_float4(hx, hy, hz, 0.f);
        }
    }
}

// ---------------- kNN query: lockstep scan + chunk-bbox pruning ----------------
// 128 threads = 32 Morton-adjacent queries (lane) x 4 split warps (chunks
// dealt round-robin). Pass 1 scans the home +-1 chunks (seeds tau); pass 2
// walks all other chunks with a per-lane box-distance test + warp ballot
// skip. tau only shrinks, so skipping is exact. score = 0.5|p|^2 - q.p;
// d^2 threshold = 2*tau + |q|^2.
__global__ __launch_bounds__(KTHR) void knn_query_kernel()
{
    __shared__ __align__(16) unsigned char raw[20480];
    __shared__ float tau_sh[32];
    float2 (*cbuf)[KTHR] = (float2 (*)[KTHR])raw;          // 16 KB

    const unsigned FULL = 0xffffffffu;
    const int tid  = threadIdx.x;
    const int lq   = tid & 31;
    const int s    = tid >> 5;
    const int b    = blockIdx.y;
    const int sbase = blockIdx.x * 32;
    const int slot  = sbase + lq;

    const float4* pts = g_pts4 + (size_t)b * NPTS;

    float4 q4 = pts[slot];
    const float qx = q4.x, qy = q4.y, qz = q4.z;
    const float qr2 = 2.0f * q4.w;

    if (tid < 32) tau_sh[tid] = 1e30f;
    __syncthreads();

    float bd[KNN];
    int   bi[KNN];
#pragma unroll
    for (int k = 0; k < KNN; k++) { bd[k] = 1e30f; bi[k] = -1; }

    int   cnt = 0;
    float tau = 1e30f;

#define COMPACT() do {                                                        \
    for (int i = 0; i < cnt; i++) {                                           \
        float2 c = cbuf[i][tid];                                              \
        float d = c.x;                                                        \
        int  id = __float_as_int(c.y);                                        \
        if (d < bd[KNN - 1] && id != slot) {                                  \
            _Pragma("unroll")                                                 \
            for (int k = KNN - 1; k > 0; --k) {                               \
                if (bd[k] > d) {                                              \
                    bool sh = bd[k - 1] > d;                                  \
                    bd[k] = sh ? bd[k - 1] : d;                               \
                    bi[k] = sh ? bi[k - 1] : id;                              \
                }                                                             \
            }                                                                 \
            if (bd[0] > d) { bd[0] = d; bi[0] = id; }                         \
        }                                                                     \
    }                                                                         \
    cnt = 0;                                                                  \
    tau_sh[lq] = fminf(tau_sh[lq], bd[KNN - 1]);                              \
    tau = fminf(bd[KNN - 1], tau_sh[lq]);                                     \
} while (0)

#define SCAN_CHUNK(c) do {                                                    \
    int jb = (c) * CHUNK;                                                     \
    for (int j0 = jb; j0 < jb + CHUNK; j0 += 8) {                             \
        _Pragma("unroll")                                                     \
        for (int u = 0; u < 8; u++) {                                         \
            int j = j0 + u;                                                   \
            float4 t4 = pts[j];                                               \
            float sv = fmaf(-qz, t4.z, t4.w);                                 \
            sv = fmaf(-qy, t4.y, sv);                                         \
            sv = fmaf(-qx, t4.x, sv);                                         \
            if (sv < tau) {                                                   \
                cbuf[cnt][tid] = make_float2(sv, __int_as_float(j));          \
                cnt++;                                                        \
            }                                                                 \
        }                                                                     \
        if (__any_sync(FULL, cnt >= CBUF - 8)) COMPACT();                     \
    }                                                                         \
} while (0)

    // home range (warp-uniform)
    const int h0 = max(sbase / CHUNK - 1, 0);
    const int h1 = min((sbase + 31) / CHUNK + 1, NCH - 1);

    // pass 1: seed tau from home chunks
    for (int c = h0 + s; c <= h1; c += NSPL) SCAN_CHUNK(c);
    COMPACT();
    __syncthreads();                 // seeds visible across split warps
    tau = fminf(bd[KNN - 1], tau_sh[lq]);

    // pass 2: pruned walk over all other chunks
    for (int c = s; c < NCH; c += NSPL) {
        if (c >= h0 && c <= h1) continue;
        float4 lo = g_chlo[b][c];
        float4 hi = g_chhi[b][c];
        float dx = fmaxf(fmaxf(lo.x - qx, qx - hi.x), 0.f);
        float dy = fmaxf(fmaxf(lo.y - qy, qy - hi.y), 0.f);
        float dz = fmaxf(fmaxf(lo.z - qz, qz - hi.z), 0.f);
        float d2box = fmaf(dx, dx, fmaf(dy, dy, dz * dz));
        float thr = fmaf(2.0f, tau, qr2) * 1.0002f;
        if (__any_sync(FULL, d2box < thr)) SCAN_CHUNK(c);
    }
    COMPACT();
#undef SCAN_CHUNK
#undef COMPACT

    __syncthreads();   // reuse raw for the 4-way merge
    float* md = (float*)raw;                         // 80*32*4 = 10240 B
    int*   mi = (int*)(raw + NSPL * KNN * 32 * 4);   // 10240 B
#pragma unroll
    for (int k = 0; k < KNN; k++) {
        md[(s * KNN + k) * 32 + lq] = bd[k];
        mi[(s * KNN + k) * 32 + lq] = bi[k];
    }
    __syncthreads();

    if (tid < 32) {
        float fd[KNN]; int fi[KNN];
#pragma unroll
        for (int k = 0; k < KNN; k++) { fd[k] = 1e30f; fi[k] = -1; }
        for (int i = 0; i < NSPL * KNN; i++) {
            float d = md[i * 32 + tid];
            int  id = mi[i * 32 + tid];
            if (d < fd[KNN - 1]) {
#pragma unroll
                for (int k = KNN - 1; k > 0; --k) {
                    if (fd[k] > d) {
                        bool sh = fd[k - 1] > d;
                        fd[k] = sh ? fd[k - 1] : d;
                        fi[k] = sh ? fi[k - 1] : id;
                    }
                }
                if (fd[0] > d) { fd[0] = d; fi[0] = id; }
            }
        }
        const int* ids = g_ids + (size_t)b * NPTS;
        int myslot = sbase + tid;
        int* o = g_knn + ((size_t)b * NPTS + ids[myslot]) * KNN;
#pragma unroll
        for (int k = 0; k < KNN; k++) o[k] = ids[fi[k]];
    }
}

// ---------------- setup: cond MLP + folded per-batch vectors ----------------
__global__ __launch_bounds__(256) void setup_kernel(
    const float* __restrict__ t, const float* __restrict__ conditioning,
    const float* __restrict__ Wc1, const float* __restrict__ bc1,
    const float* __restrict__ Wc2, const float* __restrict__ bc2,
    const float* __restrict__ Wc3, const float* __restrict__ bc3,
    const float* __restrict__ We1, const float* __restrict__ be1,
    const float* __restrict__ Wn1, const float* __restrict__ bn1)
{
    const unsigned FULL = 0xffffffffu;
    const int tid  = threadIdx.x;
    const int lane = tid & 31;
    const int warp = tid >> 5;

    if (tid < 128) {
        float s1 = 0.f, s2 = 0.f;
#pragma unroll
        for (int c = 0; c < 36; c++) {
            s1 += We1[c * 128 + tid];
            s2 += We1[(36 + c) * 128 + tid];
        }
        g_S1[tid] = s1;
        g_S2[tid] = s2;
    }
    if (tid < 64) {
        float sn = 0.f;
#pragma unroll
        for (int c = 0; c < 36; c++) sn += Wn1[c * 64 + tid];
        g_SN[tid] = sn;
    }

    __shared__ float sc[36], h1[144], h2[144], cv[40];

    for (int b = 0; b < NB; b++) {
        if (tid < 36) {
            float v;
            if (tid < 16) {
                float f = expf(-logf(10000.0f) * (float)tid / 15.0f);
                v = sinf(t[b] * f);
            } else if (tid < 32) {
                int i = tid - 16;
                float f = expf(-logf(10000.0f) * (float)i / 15.0f);
                v = cosf(t[b] * f);
            } else {
                v = conditioning[b * 4 + (tid - 32)];
            }
            sc[tid] = v;
        }
        __syncthreads();
        if (tid < 144) {
            float a = bc1[tid];
#pragma unroll
            for (int c = 0; c < 36; c++) a = fmaf(sc[c], Wc1[c * 144 + tid], a);
            h1[tid] = gelu_f(a);
        }
        __syncthreads();
        for (int o = 0; o < 18; o++) {
            int j = warp + 8 * o;
            float a = 0.f;
#pragma unroll
            for (int r = 0; r < 5; r++) {
                int c = lane + 32 * r;
                if (c < 144) a = fmaf(h1[c], Wc2[c * 144 + j], a);
            }
#pragma unroll
            for (int off = 16; off > 0; off >>= 1)
                a += __shfl_xor_sync(FULL, a, off);
            if (lane == 0) h2[j] = gelu_f(a + bc2[j]);
        }
        __syncthreads();
        for (int o = 0; o < 5; o++) {
            int j = warp + 8 * o;
            if (j < 36) {
                float a = 0.f;
#pragma unroll
                for (int r = 0; r < 5; r++) {
                    int c = lane + 32 * r;
                    if (c < 144) a = fmaf(h2[c], Wc3[c * 36 + j], a);
                }
#pragma unroll
                for (int off = 16; off > 0; off >>= 1)
                    a += __shfl_xor_sync(FULL, a, off);
                if (lane == 0) cv[j] = a + bc3[j];
            }
        }
        __syncthreads();
        if (tid < 128) {
            float a = be1[tid];
#pragma unroll
            for (int c = 0; c < 36; c++)
                a = fmaf(cv[c], We1[c * 128 + tid] + We1[(36 + c) * 128 + tid], a);
            g_base1[b][tid] = a;
        }
        if (tid < 64) {
            float a = bn1[tid];
#pragma unroll
            for (int c = 0; c < 36; c++) a = fmaf(cv[c], Wn1[c * 64 + tid], a);
            g_baseN[b][tid] = a;
        }
        __syncthreads();
    }
}

// ---------------- main: edge MLP + softmax + aggregation + node MLP ----------------
__global__ __launch_bounds__(256) void main_kernel(
    const float* __restrict__ z,
    const float* __restrict__ We1, const float* __restrict__ We2,
    const float* __restrict__ be2,
    const float* __restrict__ Wn1, const float* __restrict__ Wn2,
    const float* __restrict__ bn2,
    const float* __restrict__ alpha, const float* __restrict__ beta,
    float* __restrict__ out)
{
    __shared__ float4 part[8][KNN][17];

    const unsigned FULL = 0xffffffffu;
    const int wlocal = threadIdx.x >> 5;
    const int warp = (blockIdx.x * blockDim.x + threadIdx.x) >> 5;
    const int lane = threadIdx.x & 31;
    const int b = warp >> 13;
    const int n = warp & (NPTS - 1);

    const float* zb = z + (size_t)b * NPTS * 7;
    const float* zt = zb + (size_t)n * 7;
    const float ptx = zt[0], pty = zt[1], ptz = zt[2];
    const float vtx = zt[3], vty = zt[4], vtz = zt[5];
    const float mt  = zt[6];

    float relx = 0.f, rely = 0.f, relz = 0.f;
    float vsx = 0.f, vsy = 0.f, vsz = 0.f;
    float msrc = 0.f, r2 = 0.f, dvv = 0.f, dvr = 0.f, dtr = 0.f;
    if (lane < KNN) {
        int src = g_knn[(size_t)warp * KNN + lane];
        const float* zs = zb + (size_t)src * 7;
        float sx = zs[0], sy = zs[1], sz = zs[2];
        vsx = zs[3]; vsy = zs[4]; vsz = zs[5]; msrc = zs[6];
        relx = sx - ptx; rely = sy - pty; relz = sz - ptz;
        r2  = relx * relx + rely * rely + relz * relz;
        dvv = vsx * vtx + vsy * vty + vsz * vtz;
        dvr = vsx * relx + vsy * rely + vsz * relz;
        dtr = vtx * relx + vty * rely + vtz * relz;
    }

    float s1[4], s2[4], w72[4], w73[4], w74[4], w75[4], b1[4];
    float4 we2[4];
#pragma unroll
    for (int qq = 0; qq < 4; qq++) {
        int j = lane + 32 * qq;
        s1[qq]  = g_S1[j];
        s2[qq]  = g_S2[j];
        w72[qq] = We1[72 * 128 + j];
        w73[qq] = We1[73 * 128 + j];
        w74[qq] = We1[74 * 128 + j];
        w75[qq] = We1[75 * 128 + j];
        b1[qq]  = g_base1[b][j];
        we2[qq] = ((const float4*)We2)[j];
    }

#pragma unroll
    for (int e = 0; e < KNN; e++) {
        float em   = __shfl_sync(FULL, msrc, e);
        float er2  = __shfl_sync(FULL, r2,   e);
        float edvv = __shfl_sync(FULL, dvv,  e);
        float edvr = __shfl_sync(FULL, dvr,  e);
        float edtr = __shfl_sync(FULL, dtr,  e);
        float p0 = 0.f, p1 = 0.f, p2 = 0.f, p3 = 0.f;
#pragma unroll
        for (int qq = 0; qq < 4; qq++) {
            float h = b1[qq];
            h = fmaf(em,   s1[qq],  h);
            h = fmaf(mt,   s2[qq],  h);
            h = fmaf(er2,  w72[qq], h);
            h = fmaf(edvv, w73[qq], h);
            h = fmaf(edvr, w74[qq], h);
            h = fmaf(edtr, w75[qq], h);
            float g = gelu_fast(h);
            p0 = fmaf(g, we2[qq].x, p0);
            p1 = fmaf(g, we2[qq].y, p1);
            p2 = fmaf(g, we2[qq].z, p2);
            p3 = fmaf(g, we2[qq].w, p3);
        }
        p0 += __shfl_xor_sync(FULL, p0, 16);
        p1 += __shfl_xor_sync(FULL, p1, 16);
        p2 += __shfl_xor_sync(FULL, p2, 16);
        p3 += __shfl_xor_sync(FULL, p3, 16);
        if (lane < 16) part[wlocal][e][lane] = make_float4(p0, p1, p2, p3);
    }
    __syncwarp();

    float elog = -1e30f, esmsg = 0.f, ecrel = 0.f, ecvel = 0.f;
    if (lane < KNN) {
        float4 acc = part[wlocal][lane][0];
#pragma unroll
        for (int i = 1; i < 16; i++) {
            float4 p = part[wlocal][lane][i];
            acc.x += p.x; acc.y += p.y; acc.z += p.z; acc.w += p.w;
        }
        elog  = acc.x + be2[0];
        esmsg = acc.y + be2[1];
        ecrel = acc.z + be2[2];
        ecvel = acc.w + be2[3];
    }

    float lg = (lane < KNN) ? elog : -1e30f;
    float mx = lg;
#pragma unroll
    for (int off = 16; off > 0; off >>= 1)
        mx = fmaxf(mx, __shfl_xor_sync(FULL, mx, off));
    float a = (lane < KNN) ? __expf(lg - mx) : 0.f;
    float den = a;
#pragma unroll
    for (int off = 16; off > 0; off >>= 1)
        den += __shfl_xor_sync(FULL, den, off);
    float w = a / den;

    float vmx = w * (ecrel * relx + ecvel * vsx);
    float vmy = w * (ecrel * rely + ecvel * vsy);
    float vmz = w * (ecrel * relz + ecvel * vsz);
    float sg  = w * esmsg;
#pragma unroll
    for (int off = 16; off > 0; off >>= 1) {
        vmx += __shfl_xor_sync(FULL, vmx, off);
        vmy += __shfl_xor_sync(FULL, vmy, off);
        vmz += __shfl_xor_sync(FULL, vmz, off);
        sg  += __shfl_xor_sync(FULL, sg,  off);
    }

    float acc2 = 0.f;
#pragma unroll
    for (int qq = 0; qq < 2; qq++) {
        int j = lane + 32 * qq;
        float h = g_baseN[b][j];
        h = fmaf(mt, g_SN[j], h);
        h = fmaf(sg, Wn1[36 * 64 + j], h);
        acc2 = fmaf(gelu_fast(h), Wn2[j], acc2);
    }
#pragma unroll
    for (int off = 16; off > 0; off >>= 1)
        acc2 += __shfl_xor_sync(FULL, acc2, off);

    if (lane == 0) {
        float sout = acc2 + bn2[0];
        float al = alpha[0], be = beta[0];
        float* o = out + (size_t)warp * 7;
        o[0] = ptx + (ptx + al * vmx);
        o[1] = pty + (pty + al * vmy);
        o[2] = ptz + (ptz + al * vmz);
        o[3] = vtx + be * vmx;
        o[4] = vty + be * vmy;
        o[5] = vtz + be * vmz;
        o[6] = mt + sout;
    }
}

// ---------------- launch ----------------
extern "C" void kernel_launch(void* const* d_in, const int* in_sizes, int n_in,
                              void* d_out, int out_size)
{
    const float* z    = (const float*)d_in[0];
    const float* t    = (const float*)d_in[1];
    const float* cond = (const float*)d_in[2];
    const float* Wc1 = (const float*)d_in[4];
    const float* bc1 = (const float*)d_in[5];
    const float* Wc2 = (const float*)d_in[6];
    const float* bc2 = (const float*)d_in[7];
    const float* Wc3 = (const float*)d_in[8];
    const float* bc3 = (const float*)d_in[9];
    const float* We1 = (const float*)d_in[10];
    const float* be1 = (const float*)d_in[11];
    const float* We2 = (const float*)d_in[12];
    const float* be2 = (const float*)d_in[13];
    const float* Wn1 = (const float*)d_in[14];
    const float* bn1 = (const float*)d_in[15];
    const float* Wn2 = (const float*)d_in[16];
    const float* bn2 = (const float*)d_in[17];
    const float* alpha = (const float*)d_in[18];
    const float* beta  = (const float*)d_in[19];
    float* out = (float*)d_out;

    grid_bbox_kernel<<<NB, 256>>>(z);
    grid_count_kernel<<<NB * NPTS / 256, 256>>>(z);
    grid_scan_kernel<<<NB, 1024>>>();
    grid_scatter_kernel<<<NB * NPTS / 256, 256>>>(z);
    chunk_bbox_kernel<<<NB, 256>>>();

    dim3 qg(NPTS / 32, NB);
    knn_query_kernel<<<qg, KTHR>>>();

    setup_kernel<<<1, 256>>>(t, cond, Wc1, bc1, Wc2, bc2, Wc3, bc3,
                             We1, be1, Wn1, bn1);

    int total_warps = NB * NPTS;
    int blocks = total_warps / 8;
    main_kernel<<<blocks, 256>>>(z, We1, We2, be2, Wn1, Wn2, bn2,
                                 alpha, beta, out);
}